// round 1
// baseline (speedup 1.0000x reference)
#include <cuda_runtime.h>
#include <cuda_bf16.h>
#include <cstdint>

// Problem constants
#define BB 2
#define SS 2048
#define HH 16
#define HD 128
#define HID 2048
#define FF 8192
#define NTOK 4096          // B*S
#define ROT 32

// ---------------- scratch (device globals; no allocation allowed) ----------
__device__ float g_ln1[(size_t)NTOK * HID];
__device__ float g_ln2[(size_t)NTOK * HID];
__device__ float g_qkv[(size_t)NTOK * 3 * HID];
__device__ float g_ctx[(size_t)NTOK * HID];
__device__ float g_att[(size_t)NTOK * HID];
__device__ float g_fc [(size_t)NTOK * FF];

// ---------------- fused double layernorm ----------------
// One block per token row (2048 elems). Produces ln1 and ln2 outputs.
__global__ void ln_kernel(const float* __restrict__ x,
                          const float* __restrict__ g1, const float* __restrict__ b1,
                          const float* __restrict__ g2, const float* __restrict__ b2,
                          float* __restrict__ o1, float* __restrict__ o2) {
    __shared__ float redS[8];
    __shared__ float redQ[8];
    const int row = blockIdx.x;
    const float* xr = x + (size_t)row * HID;
    const int t = threadIdx.x;           // 256 threads, 8 elems each
    float4 a = *(const float4*)(xr + t * 8);
    float4 b = *(const float4*)(xr + t * 8 + 4);
    float s  = a.x + a.y + a.z + a.w + b.x + b.y + b.z + b.w;
    float ss = a.x*a.x + a.y*a.y + a.z*a.z + a.w*a.w
             + b.x*b.x + b.y*b.y + b.z*b.z + b.w*b.w;
    #pragma unroll
    for (int o = 16; o; o >>= 1) {
        s  += __shfl_xor_sync(0xffffffffu, s,  o);
        ss += __shfl_xor_sync(0xffffffffu, ss, o);
    }
    if ((t & 31) == 0) { redS[t >> 5] = s; redQ[t >> 5] = ss; }
    __syncthreads();
    s = 0.f; ss = 0.f;
    #pragma unroll
    for (int i = 0; i < 8; i++) { s += redS[i]; ss += redQ[i]; }
    const float mu  = s * (1.0f / HID);
    const float var = ss * (1.0f / HID) - mu * mu;
    const float rs  = rsqrtf(var + 1e-5f);

    float vals[8] = {a.x,a.y,a.z,a.w,b.x,b.y,b.z,b.w};
    float out1[8], out2[8];
    #pragma unroll
    for (int q = 0; q < 8; q++) {
        const int col = t * 8 + q;
        const float xn = (vals[q] - mu) * rs;
        out1[q] = xn * g1[col] + b1[col];
        out2[q] = xn * g2[col] + b2[col];
    }
    float* p1 = o1 + (size_t)row * HID + t * 8;
    float* p2 = o2 + (size_t)row * HID + t * 8;
    *(float4*)(p1)     = make_float4(out1[0], out1[1], out1[2], out1[3]);
    *(float4*)(p1 + 4) = make_float4(out1[4], out1[5], out1[6], out1[7]);
    *(float4*)(p2)     = make_float4(out2[0], out2[1], out2[2], out2[3]);
    *(float4*)(p2 + 4) = make_float4(out2[4], out2[5], out2[6], out2[7]);
}

// ---------------- RoPE (in place on qkv, q & k heads, first 32 dims) -------
__global__ void rope_kernel(float* __restrict__ qkv) {
    const int t   = blockIdx.x;          // token 0..4095
    const int s   = t & (SS - 1);
    const int tid = threadIdx.x;         // 512 threads: qk(2) x head(16) x d(16)
    const int qk  = tid >> 8;
    const int hh  = (tid >> 4) & 15;
    const int d   = tid & 15;
    float* p = qkv + (size_t)t * (3 * HID) + hh * (3 * HD) + qk * HD;
    const float inv = powf(10000.0f, -(float)d * (1.0f / 16.0f));
    const float ang = (float)s * inv;
    float sn, c;
    sincosf(ang, &sn, &c);
    const float x1 = p[d];
    const float x2 = p[d + 16];
    p[d]      = x1 * c - x2 * sn;
    p[d + 16] = x2 * c + x1 * sn;
}

// ---------------- GEMM: C = A(MxK) * B(KxN) + epilogue ----------------
// BM=128, BN=64, BK=16, 256 threads, 8x4 per-thread microtile.
#define BM 128
#define BN 64
#define BK 16

__device__ __forceinline__ float gelu_exact(float v) {
    return 0.5f * v * (1.0f + erff(v * 0.70710678118654752f));
}

template <int EPI>   // 0: +bias   1: gelu(+bias)   2: +bias+add1+add2
__global__ void gemm_kernel(const float* __restrict__ A, const float* __restrict__ Bm,
                            const float* __restrict__ bias,
                            const float* __restrict__ add1, const float* __restrict__ add2,
                            float* __restrict__ C, int M, int N, int K) {
    __shared__ float As[BK][BM + 4];
    __shared__ float Bs[BK][BN];
    const int tid = threadIdx.x;
    const int bx = blockIdx.x, by = blockIdx.y;
    const int ty = tid >> 4, tx = tid & 15;

    float acc[8][4];
    #pragma unroll
    for (int i = 0; i < 8; i++)
        #pragma unroll
        for (int j = 0; j < 4; j++) acc[i][j] = 0.f;

    const float* Ablk = A + (size_t)by * BM * K;
    const float* Bblk = Bm + (size_t)bx * BN;
    const int ar = tid >> 2;            // 0..63
    const int ac = (tid & 3) * 4;       // 0,4,8,12
    const int br = tid >> 4;            // 0..15
    const int bc = (tid & 15) * 4;      // 0..60

    for (int k0 = 0; k0 < K; k0 += BK) {
        const float4 a0 = *(const float4*)(Ablk + (size_t)ar        * K + k0 + ac);
        const float4 a1 = *(const float4*)(Ablk + (size_t)(ar + 64) * K + k0 + ac);
        const float4 b0 = *(const float4*)(Bblk + (size_t)(k0 + br) * N + bc);
        __syncthreads();
        As[ac + 0][ar] = a0.x; As[ac + 1][ar] = a0.y;
        As[ac + 2][ar] = a0.z; As[ac + 3][ar] = a0.w;
        As[ac + 0][ar + 64] = a1.x; As[ac + 1][ar + 64] = a1.y;
        As[ac + 2][ar + 64] = a1.z; As[ac + 3][ar + 64] = a1.w;
        *(float4*)&Bs[br][bc] = b0;
        __syncthreads();
        #pragma unroll
        for (int kk = 0; kk < BK; kk++) {
            const float4 av0 = *(const float4*)&As[kk][ty * 8];
            const float4 av1 = *(const float4*)&As[kk][ty * 8 + 4];
            const float4 bv  = *(const float4*)&Bs[kk][tx * 4];
            const float aa[8] = {av0.x, av0.y, av0.z, av0.w, av1.x, av1.y, av1.z, av1.w};
            const float bb[4] = {bv.x, bv.y, bv.z, bv.w};
            #pragma unroll
            for (int i = 0; i < 8; i++)
                #pragma unroll
                for (int j = 0; j < 4; j++)
                    acc[i][j] += aa[i] * bb[j];
        }
    }

    const int row0 = by * BM + ty * 8;
    const int col0 = bx * BN + tx * 4;
    const float4 bi = *(const float4*)(bias + col0);
    const float bias4[4] = {bi.x, bi.y, bi.z, bi.w};
    #pragma unroll
    for (int i = 0; i < 8; i++) {
        const size_t off = (size_t)(row0 + i) * N + col0;
        float v[4];
        #pragma unroll
        for (int j = 0; j < 4; j++) v[j] = acc[i][j] + bias4[j];
        if (EPI == 1) {
            #pragma unroll
            for (int j = 0; j < 4; j++) v[j] = gelu_exact(v[j]);
        }
        if (EPI == 2) {
            const float4 x1 = *(const float4*)(add1 + off);
            const float4 x2 = *(const float4*)(add2 + off);
            v[0] += x1.x + x2.x; v[1] += x1.y + x2.y;
            v[2] += x1.z + x2.z; v[3] += x1.w + x2.w;
        }
        *(float4*)(C + off) = make_float4(v[0], v[1], v[2], v[3]);
    }
}

// ---------------- causal flash attention (fp32) ----------------
// Block: one (b,h), one 64-row q tile. 256 threads.
// Thread (g = tid>>3, j = tid&7) owns q rows {2g, 2g+1}, kc subset {j+8i},
// output dims [j*16, j*16+16).
#define TPAD 132          // smem row stride (128 + 4) — conflict-free

__global__ void attn_kernel(const float* __restrict__ qkv, float* __restrict__ ctx) {
    extern __shared__ float sm[];
    float* Qs = sm;
    float* Ks = sm + 64 * TPAD;
    float* Vs = sm + 2 * 64 * TPAD;

    const int qt = gridDim.x - 1 - blockIdx.x;    // heavy tiles first
    const int b  = blockIdx.y >> 4;
    const int h  = blockIdx.y & 15;
    const int tid = threadIdx.x;
    const int g  = tid >> 3;
    const int j  = tid & 7;
    const int row0 = 2 * g;
    const size_t tokbase = (size_t)b * SS;

    const float* qp = qkv + (tokbase + qt * 64) * (3 * HID) + h * (3 * HD);
    for (int u = tid; u < 64 * 32; u += 256) {
        const int rr = u >> 5, c4 = (u & 31) << 2;
        *(float4*)&Qs[rr * TPAD + c4] = *(const float4*)(qp + (size_t)rr * (3 * HID) + c4);
    }

    float acc0[16], acc1[16];
    #pragma unroll
    for (int i = 0; i < 16; i++) { acc0[i] = 0.f; acc1[i] = 0.f; }
    float m0 = -1e30f, m1 = -1e30f, l0 = 0.f, l1 = 0.f;
    const float scale = 0.08838834764831845f;     // 1/sqrt(128)
    const int qg0 = qt * 64 + row0;
    const int qg1 = qg0 + 1;

    for (int kt = 0; kt <= qt; ++kt) {
        __syncthreads();
        const float* kp = qkv + (tokbase + kt * 64) * (3 * HID) + h * (3 * HD) + HD;
        for (int u = tid; u < 64 * 32; u += 256) {
            const int rr = u >> 5, c4 = (u & 31) << 2;
            *(float4*)&Ks[rr * TPAD + c4] = *(const float4*)(kp + (size_t)rr * (3 * HID) + c4);
            *(float4*)&Vs[rr * TPAD + c4] = *(const float4*)(kp + HD + (size_t)rr * (3 * HID) + c4);
        }
        __syncthreads();

        float s0[8], s1[8];
        #pragma unroll
        for (int i = 0; i < 8; i++) { s0[i] = 0.f; s1[i] = 0.f; }
        #pragma unroll 4
        for (int d4 = 0; d4 < HD; d4 += 4) {
            const float4 q0 = *(const float4*)&Qs[row0 * TPAD + d4];
            const float4 q1 = *(const float4*)&Qs[(row0 + 1) * TPAD + d4];
            #pragma unroll
            for (int i = 0; i < 8; i++) {
                const float4 kv = *(const float4*)&Ks[(j + 8 * i) * TPAD + d4];
                s0[i] += q0.x * kv.x + q0.y * kv.y + q0.z * kv.z + q0.w * kv.w;
                s1[i] += q1.x * kv.x + q1.y * kv.y + q1.z * kv.z + q1.w * kv.w;
            }
        }

        const int kb = kt * 64 + j;
        #pragma unroll
        for (int i = 0; i < 8; i++) {
            const int kg = kb + 8 * i;
            s0[i] = (kg <= qg0) ? s0[i] * scale : -1e30f;
            s1[i] = (kg <= qg1) ? s1[i] * scale : -1e30f;
        }
        float lm0 = s0[0], lm1 = s1[0];
        #pragma unroll
        for (int i = 1; i < 8; i++) { lm0 = fmaxf(lm0, s0[i]); lm1 = fmaxf(lm1, s1[i]); }
        #pragma unroll
        for (int o = 1; o < 8; o <<= 1) {
            lm0 = fmaxf(lm0, __shfl_xor_sync(0xffffffffu, lm0, o, 8));
            lm1 = fmaxf(lm1, __shfl_xor_sync(0xffffffffu, lm1, o, 8));
        }
        const float mn0 = fmaxf(m0, lm0);
        const float mn1 = fmaxf(m1, lm1);
        const float c0 = __expf(m0 - mn0);
        const float c1 = __expf(m1 - mn1);
        m0 = mn0; m1 = mn1;
        float ps0 = 0.f, ps1 = 0.f;
        #pragma unroll
        for (int i = 0; i < 8; i++) {
            s0[i] = __expf(s0[i] - mn0); ps0 += s0[i];
            s1[i] = __expf(s1[i] - mn1); ps1 += s1[i];
        }
        l0 = l0 * c0 + ps0;
        l1 = l1 * c1 + ps1;
        #pragma unroll
        for (int dd = 0; dd < 16; dd++) { acc0[dd] *= c0; acc1[dd] *= c1; }

        for (int i = 0; i < 8; i++) {
            #pragma unroll
            for (int jj = 0; jj < 8; jj++) {
                const float p0 = __shfl_sync(0xffffffffu, s0[i], jj, 8);
                const float p1 = __shfl_sync(0xffffffffu, s1[i], jj, 8);
                const float* vr = &Vs[(jj + 8 * i) * TPAD + j * 16];
                #pragma unroll
                for (int dd = 0; dd < 16; dd++) {
                    const float vv = vr[dd];
                    acc0[dd] += p0 * vv;
                    acc1[dd] += p1 * vv;
                }
            }
        }
    }

    #pragma unroll
    for (int o = 1; o < 8; o <<= 1) {
        l0 += __shfl_xor_sync(0xffffffffu, l0, o, 8);
        l1 += __shfl_xor_sync(0xffffffffu, l1, o, 8);
    }
    const float inv0 = 1.0f / l0;
    const float inv1 = 1.0f / l1;
    float* o0 = ctx + (tokbase + qt * 64 + row0) * (size_t)HID + h * HD + j * 16;
    float* o1 = o0 + HID;
    #pragma unroll
    for (int dd = 0; dd < 16; dd += 4) {
        *(float4*)(o0 + dd) = make_float4(acc0[dd] * inv0, acc0[dd+1] * inv0,
                                          acc0[dd+2] * inv0, acc0[dd+3] * inv0);
        *(float4*)(o1 + dd) = make_float4(acc1[dd] * inv1, acc1[dd+1] * inv1,
                                          acc1[dd+2] * inv1, acc1[dd+3] * inv1);
    }
}

// ---------------- launch ----------------
extern "C" void kernel_launch(void* const* d_in, const int* in_sizes, int n_in,
                              void* d_out, int out_size) {
    const float* hid   = (const float*)d_in[0];
    const float* ln1g  = (const float*)d_in[1];
    const float* ln1b  = (const float*)d_in[2];
    const float* ln2g  = (const float*)d_in[3];
    const float* ln2b  = (const float*)d_in[4];
    const float* Wqkv  = (const float*)d_in[5];
    const float* bqkv  = (const float*)d_in[6];
    const float* Wo    = (const float*)d_in[7];
    const float* bo    = (const float*)d_in[8];
    const float* Wfc   = (const float*)d_in[9];
    const float* bfc   = (const float*)d_in[10];
    const float* Wproj = (const float*)d_in[11];
    const float* bproj = (const float*)d_in[12];
    float* out = (float*)d_out;

    float *ln1, *ln2, *qkv, *ctx, *att, *fc;
    cudaGetSymbolAddress((void**)&ln1, g_ln1);
    cudaGetSymbolAddress((void**)&ln2, g_ln2);
    cudaGetSymbolAddress((void**)&qkv, g_qkv);
    cudaGetSymbolAddress((void**)&ctx, g_ctx);
    cudaGetSymbolAddress((void**)&att, g_att);
    cudaGetSymbolAddress((void**)&fc,  g_fc);

    // 1. LN1 + LN2 fused
    ln_kernel<<<NTOK, 256>>>(hid, ln1g, ln1b, ln2g, ln2b, ln1, ln2);

    // 2. QKV = ln1 @ W_qkv + b_qkv      (4096 x 6144 x 2048)
    gemm_kernel<0><<<dim3(3 * HID / BN, NTOK / BM), 256>>>(
        ln1, Wqkv, bqkv, nullptr, nullptr, qkv, NTOK, 3 * HID, HID);

    // 3. RoPE in place on q/k (first 32 dims)
    rope_kernel<<<NTOK, 512>>>(qkv);

    // 4. causal attention -> ctx (already in (B,S,H*HD) layout)
    const int attn_smem = 3 * 64 * TPAD * (int)sizeof(float);
    cudaFuncSetAttribute(attn_kernel, cudaFuncAttributeMaxDynamicSharedMemorySize, attn_smem);
    attn_kernel<<<dim3(SS / 64, BB * HH), 256, attn_smem>>>(qkv, ctx);

    // 5. attn_out = ctx @ W_o + b_o     (4096 x 2048 x 2048)
    gemm_kernel<0><<<dim3(HID / BN, NTOK / BM), 256>>>(
        ctx, Wo, bo, nullptr, nullptr, att, NTOK, HID, HID);

    // 6. fc = gelu(ln2 @ W_fc + b_fc)   (4096 x 8192 x 2048)
    gemm_kernel<1><<<dim3(FF / BN, NTOK / BM), 256>>>(
        ln2, Wfc, bfc, nullptr, nullptr, fc, NTOK, FF, HID);

    // 7. out = fc @ W_proj + b_proj + attn_out + hidden   (4096 x 2048 x 8192)
    gemm_kernel<2><<<dim3(HID / BN, NTOK / BM), 256>>>(
        fc, Wproj, bproj, att, hid, out, NTOK, HID, FF);
}

// round 3
// speedup vs baseline: 2.7603x; 2.7603x over previous
#include <cuda_runtime.h>
#include <cuda_bf16.h>
#include <cstdint>

// Problem constants
#define BB 2
#define SS 2048
#define HH 16
#define HD 128
#define HID 2048
#define FF 8192
#define NTOK 4096

typedef __nv_bfloat16 bf16;

// ---------------- scratch (device globals; no allocation allowed) ----------
__device__ float g_qkv[(size_t)NTOK * 3 * HID];
__device__ float g_att[(size_t)NTOK * HID];
__device__ bf16 g_ln1h[(size_t)NTOK * HID];
__device__ bf16 g_ln1l[(size_t)NTOK * HID];
__device__ bf16 g_ln2h[(size_t)NTOK * HID];
__device__ bf16 g_ln2l[(size_t)NTOK * HID];
__device__ bf16 g_ctxh[(size_t)NTOK * HID];
__device__ bf16 g_ctxl[(size_t)NTOK * HID];
__device__ bf16 g_fch[(size_t)NTOK * FF];
__device__ bf16 g_fcl[(size_t)NTOK * FF];
__device__ bf16 g_wqkvh[(size_t)3 * HID * HID];
__device__ bf16 g_wqkvl[(size_t)3 * HID * HID];
__device__ bf16 g_woh[(size_t)HID * HID];
__device__ bf16 g_wol[(size_t)HID * HID];
__device__ bf16 g_wfch[(size_t)FF * HID];
__device__ bf16 g_wfcl[(size_t)FF * HID];
__device__ bf16 g_wprojh[(size_t)HID * FF];
__device__ bf16 g_wprojl[(size_t)HID * FF];

// ---------------- helpers ----------------
__device__ __forceinline__ uint32_t smem_u32(const void* p) {
    uint32_t a;
    asm("{ .reg .u64 t; cvta.to.shared.u64 t, %1; cvt.u32.u64 %0, t; }" : "=r"(a) : "l"(p));
    return a;
}
#define CP16(dst, src) \
    asm volatile("cp.async.cg.shared.global [%0], [%1], 16;" :: "r"(dst), "l"(src) : "memory")
#define CP_COMMIT() asm volatile("cp.async.commit_group;" ::: "memory")
#define CP_WAIT1()  asm volatile("cp.async.wait_group 1;" ::: "memory")
#define CP_WAIT0()  asm volatile("cp.async.wait_group 0;" ::: "memory")

__device__ __forceinline__ void ldm_x4(uint32_t* r, uint32_t addr) {
    asm volatile("ldmatrix.sync.aligned.m8n8.x4.shared.b16 {%0,%1,%2,%3}, [%4];"
                 : "=r"(r[0]), "=r"(r[1]), "=r"(r[2]), "=r"(r[3]) : "r"(addr));
}
__device__ __forceinline__ void mma_bf16(float* c, const uint32_t* a, const uint32_t* b) {
    asm volatile("mma.sync.aligned.m16n8k16.row.col.f32.bf16.bf16.f32 "
                 "{%0,%1,%2,%3},{%4,%5,%6,%7},{%8,%9},{%0,%1,%2,%3};"
                 : "+f"(c[0]), "+f"(c[1]), "+f"(c[2]), "+f"(c[3])
                 : "r"(a[0]), "r"(a[1]), "r"(a[2]), "r"(a[3]), "r"(b[0]), "r"(b[1]));
}
__device__ __forceinline__ void split_bf16(float v, bf16& h, bf16& l) {
    h = __float2bfloat16(v);
    l = __float2bfloat16(v - __bfloat162float(h));
}
__device__ __forceinline__ float gelu_exact(float v) {
    return 0.5f * v * (1.0f + erff(v * 0.70710678118654752f));
}

// ---------------- fused double layernorm -> bf16 hi/lo ----------------
__global__ void ln_kernel(const float* __restrict__ x,
                          const float* __restrict__ g1, const float* __restrict__ b1,
                          const float* __restrict__ g2, const float* __restrict__ b2,
                          bf16* __restrict__ o1h, bf16* __restrict__ o1l,
                          bf16* __restrict__ o2h, bf16* __restrict__ o2l) {
    __shared__ float redS[8];
    __shared__ float redQ[8];
    const int row = blockIdx.x;
    const float* xr = x + (size_t)row * HID;
    const int t = threadIdx.x;
    float4 a = *(const float4*)(xr + t * 8);
    float4 b = *(const float4*)(xr + t * 8 + 4);
    float s  = a.x + a.y + a.z + a.w + b.x + b.y + b.z + b.w;
    float ss = a.x*a.x + a.y*a.y + a.z*a.z + a.w*a.w
             + b.x*b.x + b.y*b.y + b.z*b.z + b.w*b.w;
    #pragma unroll
    for (int o = 16; o; o >>= 1) {
        s  += __shfl_xor_sync(0xffffffffu, s,  o);
        ss += __shfl_xor_sync(0xffffffffu, ss, o);
    }
    if ((t & 31) == 0) { redS[t >> 5] = s; redQ[t >> 5] = ss; }
    __syncthreads();
    s = 0.f; ss = 0.f;
    #pragma unroll
    for (int i = 0; i < 8; i++) { s += redS[i]; ss += redQ[i]; }
    const float mu  = s * (1.0f / HID);
    const float var = ss * (1.0f / HID) - mu * mu;
    const float rs  = rsqrtf(var + 1e-5f);

    float vals[8] = {a.x,a.y,a.z,a.w,b.x,b.y,b.z,b.w};
    __align__(16) bf16 h1[8], l1[8], h2[8], l2[8];
    #pragma unroll
    for (int q = 0; q < 8; q++) {
        const int col = t * 8 + q;
        const float xn = (vals[q] - mu) * rs;
        split_bf16(xn * g1[col] + b1[col], h1[q], l1[q]);
        split_bf16(xn * g2[col] + b2[col], h2[q], l2[q]);
    }
    const size_t off = (size_t)row * HID + t * 8;
    *(uint4*)(o1h + off) = *(uint4*)h1;
    *(uint4*)(o1l + off) = *(uint4*)l1;
    *(uint4*)(o2h + off) = *(uint4*)h2;
    *(uint4*)(o2l + off) = *(uint4*)l2;
}

// ---------------- weight convert + transpose: W[K][N] -> T{h,l}[N][K] ------
__global__ void wconv_kernel(const float* __restrict__ W, bf16* __restrict__ Th,
                             bf16* __restrict__ Tl, int K, int N) {
    __shared__ float tile[32][33];
    const int n0 = blockIdx.x * 32, k0 = blockIdx.y * 32;
    const int tx = threadIdx.x, ty = threadIdx.y;  // 32 x 8
    #pragma unroll
    for (int i = 0; i < 4; i++)
        tile[ty + 8 * i][tx] = W[(size_t)(k0 + ty + 8 * i) * N + n0 + tx];
    __syncthreads();
    #pragma unroll
    for (int i = 0; i < 4; i++) {
        const float v = tile[tx][ty + 8 * i];
        const size_t idx = (size_t)(n0 + ty + 8 * i) * K + k0 + tx;
        bf16 h, l;
        split_bf16(v, h, l);
        Th[idx] = h; Tl[idx] = l;
    }
}

// ---------------- RoPE (in place on qkv, q & k heads, first 32 dims) -------
__global__ void rope_kernel(float* __restrict__ qkv) {
    const int t   = blockIdx.x;
    const int s   = t & (SS - 1);
    const int tid = threadIdx.x;
    const int qk  = tid >> 8;
    const int hh  = (tid >> 4) & 15;
    const int d   = tid & 15;
    float* p = qkv + (size_t)t * (3 * HID) + hh * (3 * HD) + qk * HD;
    const float inv = powf(10000.0f, -(float)d * (1.0f / 16.0f));
    const float ang = (float)s * inv;
    float sn, c;
    sincosf(ang, &sn, &c);
    const float x1 = p[d];
    const float x2 = p[d + 16];
    p[d]      = x1 * c - x2 * sn;
    p[d + 16] = x2 * c + x1 * sn;
}

// ---------------- mma.sync bf16-split GEMM ----------------
// C[M,N] = A[M,K] * B^T  (B stored as T[N][K]).  CTA tile 128x128, BK=32.
// D = Ah*Bh + Al*Bh + Ah*Bl (fp32 accum).
// smem per stage: 4 arrays x [128][40] bf16 = 40960 B;  2 stages = 81920 B.
#define ROWP   40
#define ARR_B  10240u
#define STG_B  40960u
#define G_SMEM (2u * STG_B)

template <int EPI>  // 0: +bias->f32   1: gelu(+bias)->bf16 hi/lo   2: +bias+add1+add2->f32
__global__ void __launch_bounds__(256, 1) mma_gemm(
    const bf16* __restrict__ Ah, const bf16* __restrict__ Al,
    const bf16* __restrict__ Bh, const bf16* __restrict__ Bl,
    const float* __restrict__ bias,
    const float* __restrict__ add1, const float* __restrict__ add2,
    float* __restrict__ Cf, bf16* __restrict__ Ch, bf16* __restrict__ Cl,
    int N, int K) {
    extern __shared__ char sm[];
    const uint32_t smb = smem_u32(sm);
    const int tid = threadIdx.x;
    const int lane = tid & 31;
    const int wm = (tid >> 5) & 3;     // warp row (32 rows)
    const int wn = (tid >> 7);         // warp col (64 cols)

    const size_t arow0 = (size_t)blockIdx.x * 128;
    const size_t brow0 = (size_t)blockIdx.y * 128;
    const bf16* pa_h = Ah + arow0 * K;
    const bf16* pa_l = Al + arow0 * K;
    const bf16* pb_h = Bh + brow0 * K;
    const bf16* pb_l = Bl + brow0 * K;
    const int nch = K >> 5;

    // per-thread load coords: chunk c in [0,512): row=c>>2, 16B-chunk cc=c&3
    const int c0r = tid >> 2,          c0c = tid & 3;
    const int c1r = (tid + 256) >> 2,  c1c = tid & 3;

    // ldmatrix base offsets (bytes within a stage)
    const uint32_t aoff = ((wm * 32 + (lane & 15)) * ROWP + (lane >> 4) * 8) * 2;
    const uint32_t boff = ((wn * 64 + (lane & 7) + ((lane >> 4) & 1) * 8) * ROWP
                           + ((lane >> 3) & 1) * 8) * 2;

    float acc[2][8][4];
    #pragma unroll
    for (int m = 0; m < 2; m++)
        #pragma unroll
        for (int n = 0; n < 8; n++)
            #pragma unroll
            for (int q = 0; q < 4; q++) acc[m][n][q] = 0.f;

    // stage loader
    auto load_stage = [&](int stg, int k0) {
        const uint32_t sb = smb + (uint32_t)stg * STG_B;
        const bf16* srcs[4] = {pa_h, pa_l, pb_h, pb_l};
        #pragma unroll
        for (int a4 = 0; a4 < 4; ++a4) {
            const bf16* sp = srcs[a4];
            const uint32_t db = sb + a4 * ARR_B;
            CP16(db + (uint32_t)(c0r * ROWP + c0c * 8) * 2,
                 sp + (size_t)c0r * K + k0 + c0c * 8);
            CP16(db + (uint32_t)(c1r * ROWP + c1c * 8) * 2,
                 sp + (size_t)c1r * K + k0 + c1c * 8);
        }
    };

    load_stage(0, 0);
    CP_COMMIT();

    for (int c = 0; c < nch; ++c) {
        if (c + 1 < nch) {
            load_stage((c + 1) & 1, (c + 1) << 5);
            CP_COMMIT();
            CP_WAIT1();
        } else {
            CP_WAIT0();
        }
        __syncthreads();

        const uint32_t sb = smb + (uint32_t)(c & 1) * STG_B;
        #pragma unroll
        for (int ks = 0; ks < 2; ++ks) {
            const uint32_t kb = ks * 32;       // 16 elems * 2B
            uint32_t ah[2][4], xf[2][4], bh[4][4], bl[4][4];
            ldm_x4(ah[0], sb + aoff + kb);
            ldm_x4(ah[1], sb + aoff + kb + 16 * ROWP * 2);
            #pragma unroll
            for (int t2 = 0; t2 < 4; ++t2)
                ldm_x4(bh[t2], sb + 2 * ARR_B + boff + kb + t2 * 16 * ROWP * 2);
            // pass 1: Ah * Bh
            #pragma unroll
            for (int m = 0; m < 2; ++m)
                #pragma unroll
                for (int n = 0; n < 8; ++n)
                    mma_bf16(acc[m][n], ah[m], &bh[n >> 1][(n & 1) * 2]);
            // pass 2: Al * Bh
            ldm_x4(xf[0], sb + ARR_B + aoff + kb);
            ldm_x4(xf[1], sb + ARR_B + aoff + kb + 16 * ROWP * 2);
            #pragma unroll
            for (int m = 0; m < 2; ++m)
                #pragma unroll
                for (int n = 0; n < 8; ++n)
                    mma_bf16(acc[m][n], xf[m], &bh[n >> 1][(n & 1) * 2]);
            // pass 3: Ah * Bl
            #pragma unroll
            for (int t2 = 0; t2 < 4; ++t2)
                ldm_x4(bl[t2], sb + 3 * ARR_B + boff + kb + t2 * 16 * ROWP * 2);
            #pragma unroll
            for (int m = 0; m < 2; ++m)
                #pragma unroll
                for (int n = 0; n < 8; ++n)
                    mma_bf16(acc[m][n], ah[m], &bl[n >> 1][(n & 1) * 2]);
        }
        __syncthreads();
    }

    // epilogue
    const int row_base = blockIdx.x * 128 + wm * 32;
    const int col_base = blockIdx.y * 128 + wn * 64;
    #pragma unroll
    for (int m = 0; m < 2; ++m) {
        const int r0 = row_base + m * 16 + (lane >> 2);
        #pragma unroll
        for (int n = 0; n < 8; ++n) {
            const int cc = col_base + n * 8 + (lane & 3) * 2;
            const float b0 = bias[cc], b1 = bias[cc + 1];
            float v0 = acc[m][n][0] + b0, v1 = acc[m][n][1] + b1;
            float v2 = acc[m][n][2] + b0, v3 = acc[m][n][3] + b1;
            const size_t off0 = (size_t)r0 * N + cc;
            const size_t off1 = (size_t)(r0 + 8) * N + cc;
            if (EPI == 1) {
                bf16 h, l;
                __nv_bfloat162 hv, lv;
                split_bf16(gelu_exact(v0), h, l); hv.x = h; lv.x = l;
                split_bf16(gelu_exact(v1), h, l); hv.y = h; lv.y = l;
                *(__nv_bfloat162*)(Ch + off0) = hv;
                *(__nv_bfloat162*)(Cl + off0) = lv;
                split_bf16(gelu_exact(v2), h, l); hv.x = h; lv.x = l;
                split_bf16(gelu_exact(v3), h, l); hv.y = h; lv.y = l;
                *(__nv_bfloat162*)(Ch + off1) = hv;
                *(__nv_bfloat162*)(Cl + off1) = lv;
            } else {
                if (EPI == 2) {
                    const float2 x0 = *(const float2*)(add1 + off0);
                    const float2 y0 = *(const float2*)(add2 + off0);
                    const float2 x1 = *(const float2*)(add1 + off1);
                    const float2 y1 = *(const float2*)(add2 + off1);
                    v0 += x0.x + y0.x; v1 += x0.y + y0.y;
                    v2 += x1.x + y1.x; v3 += x1.y + y1.y;
                }
                *(float2*)(Cf + off0) = make_float2(v0, v1);
                *(float2*)(Cf + off1) = make_float2(v2, v3);
            }
        }
    }
}

// ---------------- causal flash attention (fp32) ----------------
#define TPAD 132

__global__ void attn_kernel(const float* __restrict__ qkv,
                            bf16* __restrict__ ctxh, bf16* __restrict__ ctxl) {
    extern __shared__ float smf[];
    float* Qs = smf;
    float* Ks = smf + 64 * TPAD;
    float* Vs = smf + 2 * 64 * TPAD;

    const int qt = gridDim.x - 1 - blockIdx.x;
    const int b  = blockIdx.y >> 4;
    const int h  = blockIdx.y & 15;
    const int tid = threadIdx.x;
    const int g  = tid >> 3;
    const int j  = tid & 7;
    const int row0 = 2 * g;
    const size_t tokbase = (size_t)b * SS;

    const float* qp = qkv + (tokbase + qt * 64) * (3 * HID) + h * (3 * HD);
    for (int u = tid; u < 64 * 32; u += 256) {
        const int rr = u >> 5, c4 = (u & 31) << 2;
        *(float4*)&Qs[rr * TPAD + c4] = *(const float4*)(qp + (size_t)rr * (3 * HID) + c4);
    }

    float acc0[16], acc1[16];
    #pragma unroll
    for (int i = 0; i < 16; i++) { acc0[i] = 0.f; acc1[i] = 0.f; }
    float m0 = -1e30f, m1 = -1e30f, l0 = 0.f, l1 = 0.f;
    const float scale = 0.08838834764831845f;
    const int qg0 = qt * 64 + row0;
    const int qg1 = qg0 + 1;

    for (int kt = 0; kt <= qt; ++kt) {
        __syncthreads();
        const float* kp = qkv + (tokbase + kt * 64) * (3 * HID) + h * (3 * HD) + HD;
        for (int u = tid; u < 64 * 32; u += 256) {
            const int rr = u >> 5, c4 = (u & 31) << 2;
            *(float4*)&Ks[rr * TPAD + c4] = *(const float4*)(kp + (size_t)rr * (3 * HID) + c4);
            *(float4*)&Vs[rr * TPAD + c4] = *(const float4*)(kp + HD + (size_t)rr * (3 * HID) + c4);
        }
        __syncthreads();

        float s0[8], s1[8];
        #pragma unroll
        for (int i = 0; i < 8; i++) { s0[i] = 0.f; s1[i] = 0.f; }
        #pragma unroll 4
        for (int d4 = 0; d4 < HD; d4 += 4) {
            const float4 q0 = *(const float4*)&Qs[row0 * TPAD + d4];
            const float4 q1 = *(const float4*)&Qs[(row0 + 1) * TPAD + d4];
            #pragma unroll
            for (int i = 0; i < 8; i++) {
                const float4 kv = *(const float4*)&Ks[(j + 8 * i) * TPAD + d4];
                s0[i] += q0.x * kv.x + q0.y * kv.y + q0.z * kv.z + q0.w * kv.w;
                s1[i] += q1.x * kv.x + q1.y * kv.y + q1.z * kv.z + q1.w * kv.w;
            }
        }

        const int kb = kt * 64 + j;
        #pragma unroll
        for (int i = 0; i < 8; i++) {
            const int kg = kb + 8 * i;
            s0[i] = (kg <= qg0) ? s0[i] * scale : -1e30f;
            s1[i] = (kg <= qg1) ? s1[i] * scale : -1e30f;
        }
        float lm0 = s0[0], lm1 = s1[0];
        #pragma unroll
        for (int i = 1; i < 8; i++) { lm0 = fmaxf(lm0, s0[i]); lm1 = fmaxf(lm1, s1[i]); }
        #pragma unroll
        for (int o = 1; o < 8; o <<= 1) {
            lm0 = fmaxf(lm0, __shfl_xor_sync(0xffffffffu, lm0, o, 8));
            lm1 = fmaxf(lm1, __shfl_xor_sync(0xffffffffu, lm1, o, 8));
        }
        const float mn0 = fmaxf(m0, lm0);
        const float mn1 = fmaxf(m1, lm1);
        const float c0 = __expf(m0 - mn0);
        const float c1 = __expf(m1 - mn1);
        m0 = mn0; m1 = mn1;
        float ps0 = 0.f, ps1 = 0.f;
        #pragma unroll
        for (int i = 0; i < 8; i++) {
            s0[i] = __expf(s0[i] - mn0); ps0 += s0[i];
            s1[i] = __expf(s1[i] - mn1); ps1 += s1[i];
        }
        l0 = l0 * c0 + ps0;
        l1 = l1 * c1 + ps1;
        #pragma unroll
        for (int dd = 0; dd < 16; dd++) { acc0[dd] *= c0; acc1[dd] *= c1; }

        for (int i = 0; i < 8; i++) {
            #pragma unroll
            for (int jj = 0; jj < 8; jj++) {
                const float p0 = __shfl_sync(0xffffffffu, s0[i], jj, 8);
                const float p1 = __shfl_sync(0xffffffffu, s1[i], jj, 8);
                const float* vr = &Vs[(jj + 8 * i) * TPAD + j * 16];
                #pragma unroll
                for (int dd = 0; dd < 16; dd++) {
                    const float vv = vr[dd];
                    acc0[dd] += p0 * vv;
                    acc1[dd] += p1 * vv;
                }
            }
        }
    }

    #pragma unroll
    for (int o = 1; o < 8; o <<= 1) {
        l0 += __shfl_xor_sync(0xffffffffu, l0, o, 8);
        l1 += __shfl_xor_sync(0xffffffffu, l1, o, 8);
    }
    const float inv0 = 1.0f / l0;
    const float inv1 = 1.0f / l1;
    const size_t o0 = (tokbase + qt * 64 + row0) * (size_t)HID + h * HD + j * 16;
    const size_t o1 = o0 + HID;
    __align__(16) bf16 h0[16], lo0[16], h1[16], lo1[16];
    #pragma unroll
    for (int dd = 0; dd < 16; dd++) {
        split_bf16(acc0[dd] * inv0, h0[dd], lo0[dd]);
        split_bf16(acc1[dd] * inv1, h1[dd], lo1[dd]);
    }
    *(uint4*)(ctxh + o0)     = *(uint4*)(h0);
    *(uint4*)(ctxh + o0 + 8) = *(uint4*)(h0 + 8);
    *(uint4*)(ctxl + o0)     = *(uint4*)(lo0);
    *(uint4*)(ctxl + o0 + 8) = *(uint4*)(lo0 + 8);
    *(uint4*)(ctxh + o1)     = *(uint4*)(h1);
    *(uint4*)(ctxh + o1 + 8) = *(uint4*)(h1 + 8);
    *(uint4*)(ctxl + o1)     = *(uint4*)(lo1);
    *(uint4*)(ctxl + o1 + 8) = *(uint4*)(lo1 + 8);
}

// ---------------- launch ----------------
extern "C" void kernel_launch(void* const* d_in, const int* in_sizes, int n_in,
                              void* d_out, int out_size) {
    const float* hid   = (const float*)d_in[0];
    const float* ln1g  = (const float*)d_in[1];
    const float* ln1b  = (const float*)d_in[2];
    const float* ln2g  = (const float*)d_in[3];
    const float* ln2b  = (const float*)d_in[4];
    const float* Wqkv  = (const float*)d_in[5];
    const float* bqkv  = (const float*)d_in[6];
    const float* Wo    = (const float*)d_in[7];
    const float* bo    = (const float*)d_in[8];
    const float* Wfc   = (const float*)d_in[9];
    const float* bfc   = (const float*)d_in[10];
    const float* Wproj = (const float*)d_in[11];
    const float* bproj = (const float*)d_in[12];
    float* out = (float*)d_out;

    float *qkv, *att;
    bf16 *ln1h, *ln1l, *ln2h, *ln2l, *ctxh, *ctxl, *fch, *fcl;
    bf16 *wqkvh, *wqkvl, *woh, *wol, *wfch, *wfcl, *wprojh, *wprojl;
    cudaGetSymbolAddress((void**)&qkv, g_qkv);
    cudaGetSymbolAddress((void**)&att, g_att);
    cudaGetSymbolAddress((void**)&ln1h, g_ln1h);
    cudaGetSymbolAddress((void**)&ln1l, g_ln1l);
    cudaGetSymbolAddress((void**)&ln2h, g_ln2h);
    cudaGetSymbolAddress((void**)&ln2l, g_ln2l);
    cudaGetSymbolAddress((void**)&ctxh, g_ctxh);
    cudaGetSymbolAddress((void**)&ctxl, g_ctxl);
    cudaGetSymbolAddress((void**)&fch, g_fch);
    cudaGetSymbolAddress((void**)&fcl, g_fcl);
    cudaGetSymbolAddress((void**)&wqkvh, g_wqkvh);
    cudaGetSymbolAddress((void**)&wqkvl, g_wqkvl);
    cudaGetSymbolAddress((void**)&woh, g_woh);
    cudaGetSymbolAddress((void**)&wol, g_wol);
    cudaGetSymbolAddress((void**)&wfch, g_wfch);
    cudaGetSymbolAddress((void**)&wfcl, g_wfcl);
    cudaGetSymbolAddress((void**)&wprojh, g_wprojh);
    cudaGetSymbolAddress((void**)&wprojl, g_wprojl);

    cudaFuncSetAttribute(mma_gemm<0>, cudaFuncAttributeMaxDynamicSharedMemorySize, G_SMEM);
    cudaFuncSetAttribute(mma_gemm<1>, cudaFuncAttributeMaxDynamicSharedMemorySize, G_SMEM);
    cudaFuncSetAttribute(mma_gemm<2>, cudaFuncAttributeMaxDynamicSharedMemorySize, G_SMEM);

    // weight conversions (transpose + bf16 split)
    wconv_kernel<<<dim3(3 * HID / 32, HID / 32), dim3(32, 8)>>>(Wqkv, wqkvh, wqkvl, HID, 3 * HID);
    wconv_kernel<<<dim3(HID / 32, HID / 32),     dim3(32, 8)>>>(Wo,   woh,   wol,   HID, HID);
    wconv_kernel<<<dim3(FF / 32, HID / 32),      dim3(32, 8)>>>(Wfc,  wfch,  wfcl,  HID, FF);
    wconv_kernel<<<dim3(HID / 32, FF / 32),      dim3(32, 8)>>>(Wproj, wprojh, wprojl, FF, HID);

    // 1. LN1 + LN2 fused -> bf16 hi/lo
    ln_kernel<<<NTOK, 256>>>(hid, ln1g, ln1b, ln2g, ln2b, ln1h, ln1l, ln2h, ln2l);

    // 2. QKV = ln1 @ W_qkv + b_qkv     (4096 x 6144 x 2048) -> fp32
    mma_gemm<0><<<dim3(NTOK / 128, 3 * HID / 128), 256, G_SMEM>>>(
        ln1h, ln1l, wqkvh, wqkvl, bqkv, nullptr, nullptr, qkv, nullptr, nullptr,
        3 * HID, HID);

    // 3. RoPE in place
    rope_kernel<<<NTOK, 512>>>(qkv);

    // 4. causal attention -> ctx (bf16 hi/lo)
    const int attn_smem = 3 * 64 * TPAD * (int)sizeof(float);
    cudaFuncSetAttribute(attn_kernel, cudaFuncAttributeMaxDynamicSharedMemorySize, attn_smem);
    attn_kernel<<<dim3(SS / 64, BB * HH), 256, attn_smem>>>(qkv, ctxh, ctxl);

    // 5. attn_out = ctx @ W_o + b_o    (4096 x 2048 x 2048) -> fp32
    mma_gemm<0><<<dim3(NTOK / 128, HID / 128), 256, G_SMEM>>>(
        ctxh, ctxl, woh, wol, bo, nullptr, nullptr, att, nullptr, nullptr,
        HID, HID);

    // 6. fc = gelu(ln2 @ W_fc + b_fc)  (4096 x 8192 x 2048) -> bf16 hi/lo
    mma_gemm<1><<<dim3(NTOK / 128, FF / 128), 256, G_SMEM>>>(
        ln2h, ln2l, wfch, wfcl, bfc, nullptr, nullptr, nullptr, fch, fcl,
        FF, HID);

    // 7. out = fc @ W_proj + b_proj + attn_out + hidden   (4096 x 2048 x 8192)
    mma_gemm<2><<<dim3(NTOK / 128, HID / 128), 256, G_SMEM>>>(
        fch, fcl, wprojh, wprojl, bproj, att, hid, out, nullptr, nullptr,
        HID, FF);
}

// round 4
// speedup vs baseline: 4.3965x; 1.5928x over previous
#include <cuda_runtime.h>
#include <cuda_bf16.h>
#include <cstdint>

// Problem constants
#define BB 2
#define SS 2048
#define HH 16
#define HD 128
#define HID 2048
#define FF 8192
#define NTOK 4096

typedef __nv_bfloat16 bf16;

// ---------------- scratch (device globals; no allocation allowed) ----------
__device__ float g_qkv[(size_t)NTOK * 3 * HID];
__device__ float g_att[(size_t)NTOK * HID];
__device__ float g_rope[SS * 16 * 2];
__device__ bf16 g_ln1h[(size_t)NTOK * HID];
__device__ bf16 g_ln1l[(size_t)NTOK * HID];
__device__ bf16 g_ln2h[(size_t)NTOK * HID];
__device__ bf16 g_ln2l[(size_t)NTOK * HID];
__device__ bf16 g_ctxh[(size_t)NTOK * HID];
__device__ bf16 g_ctxl[(size_t)NTOK * HID];
__device__ bf16 g_fch[(size_t)NTOK * FF];
__device__ bf16 g_fcl[(size_t)NTOK * FF];
__device__ bf16 g_Qh[(size_t)NTOK * HID];
__device__ bf16 g_Ql[(size_t)NTOK * HID];
__device__ bf16 g_Kh[(size_t)NTOK * HID];
__device__ bf16 g_Kl[(size_t)NTOK * HID];
__device__ bf16 g_Vh[(size_t)NTOK * HID];
__device__ bf16 g_Vl[(size_t)NTOK * HID];
__device__ bf16 g_wqkvh[(size_t)3 * HID * HID];
__device__ bf16 g_wqkvl[(size_t)3 * HID * HID];
__device__ bf16 g_woh[(size_t)HID * HID];
__device__ bf16 g_wol[(size_t)HID * HID];
__device__ bf16 g_wfch[(size_t)FF * HID];
__device__ bf16 g_wfcl[(size_t)FF * HID];
__device__ bf16 g_wprojh[(size_t)HID * FF];
__device__ bf16 g_wprojl[(size_t)HID * FF];

// ---------------- helpers ----------------
__device__ __forceinline__ uint32_t smem_u32(const void* p) {
    uint32_t a;
    asm("{ .reg .u64 t; cvta.to.shared.u64 t, %1; cvt.u32.u64 %0, t; }" : "=r"(a) : "l"(p));
    return a;
}
#define CP16(dst, src) \
    asm volatile("cp.async.cg.shared.global [%0], [%1], 16;" :: "r"(dst), "l"(src) : "memory")
#define CP_COMMIT() asm volatile("cp.async.commit_group;" ::: "memory")
#define CP_WAIT1()  asm volatile("cp.async.wait_group 1;" ::: "memory")
#define CP_WAIT0()  asm volatile("cp.async.wait_group 0;" ::: "memory")

__device__ __forceinline__ void ldm_x4(uint32_t* r, uint32_t addr) {
    asm volatile("ldmatrix.sync.aligned.m8n8.x4.shared.b16 {%0,%1,%2,%3}, [%4];"
                 : "=r"(r[0]), "=r"(r[1]), "=r"(r[2]), "=r"(r[3]) : "r"(addr));
}
__device__ __forceinline__ void ldm_x4_t(uint32_t* r, uint32_t addr) {
    asm volatile("ldmatrix.sync.aligned.m8n8.x4.trans.shared.b16 {%0,%1,%2,%3}, [%4];"
                 : "=r"(r[0]), "=r"(r[1]), "=r"(r[2]), "=r"(r[3]) : "r"(addr));
}
__device__ __forceinline__ void mma_bf16(float* c, const uint32_t* a, const uint32_t* b) {
    asm volatile("mma.sync.aligned.m16n8k16.row.col.f32.bf16.bf16.f32 "
                 "{%0,%1,%2,%3},{%4,%5,%6,%7},{%8,%9},{%0,%1,%2,%3};"
                 : "+f"(c[0]), "+f"(c[1]), "+f"(c[2]), "+f"(c[3])
                 : "r"(a[0]), "r"(a[1]), "r"(a[2]), "r"(a[3]), "r"(b[0]), "r"(b[1]));
}
__device__ __forceinline__ void split_bf16(float v, bf16& h, bf16& l) {
    h = __float2bfloat16(v);
    l = __float2bfloat16(v - __bfloat162float(h));
}
__device__ __forceinline__ void packhl(float a, float b, uint32_t& hi, uint32_t& lo) {
    __nv_bfloat162 hv, lv;
    split_bf16(a, hv.x, lv.x);
    split_bf16(b, hv.y, lv.y);
    hi = *(uint32_t*)&hv;
    lo = *(uint32_t*)&lv;
}
__device__ __forceinline__ float gelu_exact(float v) {
    return 0.5f * v * (1.0f + erff(v * 0.70710678118654752f));
}

// ---------------- fused double layernorm -> bf16 hi/lo ----------------
__global__ void ln_kernel(const float* __restrict__ x,
                          const float* __restrict__ g1, const float* __restrict__ b1,
                          const float* __restrict__ g2, const float* __restrict__ b2,
                          bf16* __restrict__ o1h, bf16* __restrict__ o1l,
                          bf16* __restrict__ o2h, bf16* __restrict__ o2l) {
    __shared__ float redS[8];
    __shared__ float redQ[8];
    const int row = blockIdx.x;
    const float* xr = x + (size_t)row * HID;
    const int t = threadIdx.x;
    float4 a = *(const float4*)(xr + t * 8);
    float4 b = *(const float4*)(xr + t * 8 + 4);
    float s  = a.x + a.y + a.z + a.w + b.x + b.y + b.z + b.w;
    float ss = a.x*a.x + a.y*a.y + a.z*a.z + a.w*a.w
             + b.x*b.x + b.y*b.y + b.z*b.z + b.w*b.w;
    #pragma unroll
    for (int o = 16; o; o >>= 1) {
        s  += __shfl_xor_sync(0xffffffffu, s,  o);
        ss += __shfl_xor_sync(0xffffffffu, ss, o);
    }
    if ((t & 31) == 0) { redS[t >> 5] = s; redQ[t >> 5] = ss; }
    __syncthreads();
    s = 0.f; ss = 0.f;
    #pragma unroll
    for (int i = 0; i < 8; i++) { s += redS[i]; ss += redQ[i]; }
    const float mu  = s * (1.0f / HID);
    const float var = ss * (1.0f / HID) - mu * mu;
    const float rs  = rsqrtf(var + 1e-5f);

    float vals[8] = {a.x,a.y,a.z,a.w,b.x,b.y,b.z,b.w};
    __align__(16) bf16 h1[8], l1[8], h2[8], l2[8];
    #pragma unroll
    for (int q = 0; q < 8; q++) {
        const int col = t * 8 + q;
        const float xn = (vals[q] - mu) * rs;
        split_bf16(xn * g1[col] + b1[col], h1[q], l1[q]);
        split_bf16(xn * g2[col] + b2[col], h2[q], l2[q]);
    }
    const size_t off = (size_t)row * HID + t * 8;
    *(uint4*)(o1h + off) = *(uint4*)h1;
    *(uint4*)(o1l + off) = *(uint4*)l1;
    *(uint4*)(o2h + off) = *(uint4*)h2;
    *(uint4*)(o2l + off) = *(uint4*)l2;
}

// ---------------- weight convert + transpose: W[K][N] -> T{h,l}[N][K] ------
__global__ void wconv_kernel(const float* __restrict__ W, bf16* __restrict__ Th,
                             bf16* __restrict__ Tl, int K, int N) {
    __shared__ float tile[32][33];
    const int n0 = blockIdx.x * 32, k0 = blockIdx.y * 32;
    const int tx = threadIdx.x, ty = threadIdx.y;  // 32 x 8
    #pragma unroll
    for (int i = 0; i < 4; i++)
        tile[ty + 8 * i][tx] = W[(size_t)(k0 + ty + 8 * i) * N + n0 + tx];
    __syncthreads();
    #pragma unroll
    for (int i = 0; i < 4; i++) {
        const float v = tile[tx][ty + 8 * i];
        const size_t idx = (size_t)(n0 + ty + 8 * i) * K + k0 + tx;
        bf16 h, l;
        split_bf16(v, h, l);
        Th[idx] = h; Tl[idx] = l;
    }
}

// ---------------- RoPE cos/sin table ----------------
__global__ void rope_tab_kernel(float* __restrict__ tab) {
    const int i = blockIdx.x * 256 + threadIdx.x;   // 32768 entries
    const int s = i >> 4, fi = i & 15;
    const float inv = powf(10000.0f, -(float)fi * (1.0f / 16.0f));
    float sn, cs;
    sincosf((float)s * inv, &sn, &cs);
    tab[i * 2]     = cs;
    tab[i * 2 + 1] = sn;
}

// ---------------- qkv (fp32, token-major) -> RoPE + head-major bf16 hi/lo --
// Q scaled by 1/sqrt(HD).  Out layout: [B*H][S][HD].
__global__ void qkv2attn_kernel(const float* __restrict__ qkv,
                                const float* __restrict__ tab,
                                bf16* __restrict__ Qh, bf16* __restrict__ Ql,
                                bf16* __restrict__ Kh, bf16* __restrict__ Kl,
                                bf16* __restrict__ Vh, bf16* __restrict__ Vl) {
    const int t = blockIdx.x;
    const int b = t >> 11, s = t & (SS - 1);
    const int tid = threadIdx.x;       // 512
    const int h = tid >> 5;
    const int d0 = (tid & 31) * 4;
    const float* base = qkv + (size_t)t * (3 * HID) + h * (3 * HD);

    float4 qv = *(const float4*)(base + d0);
    float4 kv = *(const float4*)(base + HD + d0);
    float4 vv = *(const float4*)(base + 2 * HD + d0);

    if (d0 < 32) {
        const bool first = d0 < 16;
        const int pd = first ? d0 + 16 : d0 - 16;
        const float4 qp = *(const float4*)(base + pd);
        const float4 kp = *(const float4*)(base + HD + pd);
        float qa[4] = {qv.x, qv.y, qv.z, qv.w};
        float ka[4] = {kv.x, kv.y, kv.z, kv.w};
        const float qpp[4] = {qp.x, qp.y, qp.z, qp.w};
        const float kpp[4] = {kp.x, kp.y, kp.z, kp.w};
        #pragma unroll
        for (int i = 0; i < 4; i++) {
            const int fi = (d0 + i) & 15;
            const float cs = tab[(s * 16 + fi) * 2];
            const float sn = tab[(s * 16 + fi) * 2 + 1];
            if (first) {
                qa[i] = qa[i] * cs - qpp[i] * sn;
                ka[i] = ka[i] * cs - kpp[i] * sn;
            } else {
                qa[i] = qa[i] * cs + qpp[i] * sn;
                ka[i] = ka[i] * cs + kpp[i] * sn;
            }
        }
        qv = make_float4(qa[0], qa[1], qa[2], qa[3]);
        kv = make_float4(ka[0], ka[1], ka[2], ka[3]);
    }
    const float sc = 0.08838834764831845f;
    qv.x *= sc; qv.y *= sc; qv.z *= sc; qv.w *= sc;

    const size_t off = ((size_t)(b * HH + h) * SS + s) * HD + d0;
    __align__(8) bf16 hh[4], ll[4];
    split_bf16(qv.x, hh[0], ll[0]); split_bf16(qv.y, hh[1], ll[1]);
    split_bf16(qv.z, hh[2], ll[2]); split_bf16(qv.w, hh[3], ll[3]);
    *(uint2*)(Qh + off) = *(uint2*)hh; *(uint2*)(Ql + off) = *(uint2*)ll;
    split_bf16(kv.x, hh[0], ll[0]); split_bf16(kv.y, hh[1], ll[1]);
    split_bf16(kv.z, hh[2], ll[2]); split_bf16(kv.w, hh[3], ll[3]);
    *(uint2*)(Kh + off) = *(uint2*)hh; *(uint2*)(Kl + off) = *(uint2*)ll;
    split_bf16(vv.x, hh[0], ll[0]); split_bf16(vv.y, hh[1], ll[1]);
    split_bf16(vv.z, hh[2], ll[2]); split_bf16(vv.w, hh[3], ll[3]);
    *(uint2*)(Vh + off) = *(uint2*)hh; *(uint2*)(Vl + off) = *(uint2*)ll;
}

// ---------------- mma.sync bf16-split GEMM (unchanged from R3) -------------
#define ROWP   40
#define ARR_B  10240u
#define STG_B  40960u
#define G_SMEM (2u * STG_B)

template <int EPI>
__global__ void __launch_bounds__(256, 1) mma_gemm(
    const bf16* __restrict__ Ah, const bf16* __restrict__ Al,
    const bf16* __restrict__ Bh, const bf16* __restrict__ Bl,
    const float* __restrict__ bias,
    const float* __restrict__ add1, const float* __restrict__ add2,
    float* __restrict__ Cf, bf16* __restrict__ Ch, bf16* __restrict__ Cl,
    int N, int K) {
    extern __shared__ char sm[];
    const uint32_t smb = smem_u32(sm);
    const int tid = threadIdx.x;
    const int lane = tid & 31;
    const int wm = (tid >> 5) & 3;
    const int wn = (tid >> 7);

    const size_t arow0 = (size_t)blockIdx.x * 128;
    const size_t brow0 = (size_t)blockIdx.y * 128;
    const bf16* pa_h = Ah + arow0 * K;
    const bf16* pa_l = Al + arow0 * K;
    const bf16* pb_h = Bh + brow0 * K;
    const bf16* pb_l = Bl + brow0 * K;
    const int nch = K >> 5;

    const int c0r = tid >> 2,          c0c = tid & 3;
    const int c1r = (tid + 256) >> 2,  c1c = tid & 3;

    const uint32_t aoff = ((wm * 32 + (lane & 15)) * ROWP + (lane >> 4) * 8) * 2;
    const uint32_t boff = ((wn * 64 + (lane & 7) + ((lane >> 4) & 1) * 8) * ROWP
                           + ((lane >> 3) & 1) * 8) * 2;

    float acc[2][8][4];
    #pragma unroll
    for (int m = 0; m < 2; m++)
        #pragma unroll
        for (int n = 0; n < 8; n++)
            #pragma unroll
            for (int q = 0; q < 4; q++) acc[m][n][q] = 0.f;

    auto load_stage = [&](int stg, int k0) {
        const uint32_t sb = smb + (uint32_t)stg * STG_B;
        const bf16* srcs[4] = {pa_h, pa_l, pb_h, pb_l};
        #pragma unroll
        for (int a4 = 0; a4 < 4; ++a4) {
            const bf16* sp = srcs[a4];
            const uint32_t db = sb + a4 * ARR_B;
            CP16(db + (uint32_t)(c0r * ROWP + c0c * 8) * 2,
                 sp + (size_t)c0r * K + k0 + c0c * 8);
            CP16(db + (uint32_t)(c1r * ROWP + c1c * 8) * 2,
                 sp + (size_t)c1r * K + k0 + c1c * 8);
        }
    };

    load_stage(0, 0);
    CP_COMMIT();

    for (int c = 0; c < nch; ++c) {
        if (c + 1 < nch) {
            load_stage((c + 1) & 1, (c + 1) << 5);
            CP_COMMIT();
            CP_WAIT1();
        } else {
            CP_WAIT0();
        }
        __syncthreads();

        const uint32_t sb = smb + (uint32_t)(c & 1) * STG_B;
        #pragma unroll
        for (int ks = 0; ks < 2; ++ks) {
            const uint32_t kb = ks * 32;
            uint32_t ah[2][4], xf[2][4], bh[4][4], bl[4][4];
            ldm_x4(ah[0], sb + aoff + kb);
            ldm_x4(ah[1], sb + aoff + kb + 16 * ROWP * 2);
            #pragma unroll
            for (int t2 = 0; t2 < 4; ++t2)
                ldm_x4(bh[t2], sb + 2 * ARR_B + boff + kb + t2 * 16 * ROWP * 2);
            #pragma unroll
            for (int m = 0; m < 2; ++m)
                #pragma unroll
                for (int n = 0; n < 8; ++n)
                    mma_bf16(acc[m][n], ah[m], &bh[n >> 1][(n & 1) * 2]);
            ldm_x4(xf[0], sb + ARR_B + aoff + kb);
            ldm_x4(xf[1], sb + ARR_B + aoff + kb + 16 * ROWP * 2);
            #pragma unroll
            for (int m = 0; m < 2; ++m)
                #pragma unroll
                for (int n = 0; n < 8; ++n)
                    mma_bf16(acc[m][n], xf[m], &bh[n >> 1][(n & 1) * 2]);
            #pragma unroll
            for (int t2 = 0; t2 < 4; ++t2)
                ldm_x4(bl[t2], sb + 3 * ARR_B + boff + kb + t2 * 16 * ROWP * 2);
            #pragma unroll
            for (int m = 0; m < 2; ++m)
                #pragma unroll
                for (int n = 0; n < 8; ++n)
                    mma_bf16(acc[m][n], ah[m], &bl[n >> 1][(n & 1) * 2]);
        }
        __syncthreads();
    }

    const int row_base = blockIdx.x * 128 + wm * 32;
    const int col_base = blockIdx.y * 128 + wn * 64;
    #pragma unroll
    for (int m = 0; m < 2; ++m) {
        const int r0 = row_base + m * 16 + (lane >> 2);
        #pragma unroll
        for (int n = 0; n < 8; ++n) {
            const int cc = col_base + n * 8 + (lane & 3) * 2;
            const float b0 = bias[cc], b1 = bias[cc + 1];
            float v0 = acc[m][n][0] + b0, v1 = acc[m][n][1] + b1;
            float v2 = acc[m][n][2] + b0, v3 = acc[m][n][3] + b1;
            const size_t off0 = (size_t)r0 * N + cc;
            const size_t off1 = (size_t)(r0 + 8) * N + cc;
            if (EPI == 1) {
                bf16 h, l;
                __nv_bfloat162 hv, lv;
                split_bf16(gelu_exact(v0), h, l); hv.x = h; lv.x = l;
                split_bf16(gelu_exact(v1), h, l); hv.y = h; lv.y = l;
                *(__nv_bfloat162*)(Ch + off0) = hv;
                *(__nv_bfloat162*)(Cl + off0) = lv;
                split_bf16(gelu_exact(v2), h, l); hv.x = h; lv.x = l;
                split_bf16(gelu_exact(v3), h, l); hv.y = h; lv.y = l;
                *(__nv_bfloat162*)(Ch + off1) = hv;
                *(__nv_bfloat162*)(Cl + off1) = lv;
            } else {
                if (EPI == 2) {
                    const float2 x0 = *(const float2*)(add1 + off0);
                    const float2 y0 = *(const float2*)(add2 + off0);
                    const float2 x1 = *(const float2*)(add1 + off1);
                    const float2 y1 = *(const float2*)(add2 + off1);
                    v0 += x0.x + y0.x; v1 += x0.y + y0.y;
                    v2 += x1.x + y1.x; v3 += x1.y + y1.y;
                }
                *(float2*)(Cf + off0) = make_float2(v0, v1);
                *(float2*)(Cf + off1) = make_float2(v2, v3);
            }
        }
    }
}

// ---------------- causal flash attention via mma.sync ----------------
// Block: 128 threads, 4 warps; 64 q-rows for one (b,h); K/V tiles 64 wide,
// double-buffered.  All operands bf16 hi/lo (3-pass split per GEMM).
#define AST   136                       // smem row stride (bf16 elems)
#define ATILE (64 * AST * 2)            // one 64x128 tile in bytes (17408)
#define AQ_H  0
#define AQ_L  ATILE
#define ASTAGE0 (2 * ATILE)
#define ASTG_B  (4 * ATILE)             // K_h,K_l,V_h,V_l
#define A_SMEM  (2 * ATILE + 2 * ASTG_B)   // 174080 B

__global__ void __launch_bounds__(128, 1) attn_mma_kernel(
    const bf16* __restrict__ Qh, const bf16* __restrict__ Ql,
    const bf16* __restrict__ Kh, const bf16* __restrict__ Kl,
    const bf16* __restrict__ Vh, const bf16* __restrict__ Vl,
    bf16* __restrict__ ctxh, bf16* __restrict__ ctxl) {
    extern __shared__ char sm[];
    const uint32_t smb = smem_u32(sm);
    const int qt = gridDim.x - 1 - blockIdx.x;
    const int bhid = blockIdx.y;
    const int b = bhid >> 4, h = bhid & 15;
    const int tid = threadIdx.x;
    const int lane = tid & 31;
    const int w = tid >> 5;

    const size_t headbase = (size_t)bhid * SS * HD;

    // ---- async loaders ----
    auto ldq = [&]() {
        const size_t gb = headbase + (size_t)qt * 64 * HD;
        #pragma unroll
        for (int i = 0; i < 8; i++) {
            const int c = tid + i * 128;
            const int row = c >> 4, ch = c & 15;
            const uint32_t so = row * (AST * 2) + ch * 16;
            const size_t go = gb + (size_t)row * HD + ch * 8;
            CP16(smb + AQ_H + so, Qh + go);
            CP16(smb + AQ_L + so, Ql + go);
        }
    };
    auto ldkv = [&](int kt, int stg) {
        const uint32_t sb = smb + ASTAGE0 + (uint32_t)stg * ASTG_B;
        const size_t gb = headbase + (size_t)kt * 64 * HD;
        #pragma unroll
        for (int i = 0; i < 8; i++) {
            const int c = tid + i * 128;
            const int row = c >> 4, ch = c & 15;
            const uint32_t so = row * (AST * 2) + ch * 16;
            const size_t go = gb + (size_t)row * HD + ch * 8;
            CP16(sb + so,             Kh + go);
            CP16(sb + ATILE + so,     Kl + go);
            CP16(sb + 2 * ATILE + so, Vh + go);
            CP16(sb + 3 * ATILE + so, Vl + go);
        }
    };

    // per-lane ldmatrix offsets (bytes)
    const uint32_t qa_off = ((w * 16 + (lane & 15)) * AST + (lane >> 4) * 8) * 2;
    const int lm = lane >> 3, li = lane & 7;
    const uint32_t kb_off = (((lm >> 1) * 8 + li) * AST + (lm & 1) * 8) * 2;
    const uint32_t vb_off = (((lm & 1) * 8 + li) * AST + (lm >> 1) * 8) * 2;

    float oacc[16][4];
    #pragma unroll
    for (int t = 0; t < 16; t++)
        #pragma unroll
        for (int q = 0; q < 4; q++) oacc[t][q] = 0.f;
    float m0 = -1e30f, m1 = -1e30f, l0 = 0.f, l1 = 0.f;
    const int qrow0 = qt * 64 + w * 16 + (lane >> 2);
    const int qrow1 = qrow0 + 8;

    ldq();
    ldkv(0, 0);
    CP_COMMIT();

    for (int kt = 0; kt <= qt; ++kt) {
        if (kt < qt) {
            ldkv(kt + 1, (kt + 1) & 1);
            CP_COMMIT();
            CP_WAIT1();
        } else {
            CP_WAIT0();
        }
        __syncthreads();
        const uint32_t sb = smb + ASTAGE0 + (uint32_t)(kt & 1) * ASTG_B;

        // ---- S = Q K^T (3-pass hi/lo) ----
        float sacc[8][4];
        #pragma unroll
        for (int j = 0; j < 8; j++)
            #pragma unroll
            for (int q = 0; q < 4; q++) sacc[j][q] = 0.f;

        #pragma unroll
        for (int ks = 0; ks < 8; ++ks) {
            uint32_t ah[4], al[4], kfh[8][2], kfl[8][2];
            ldm_x4(ah, smb + AQ_H + qa_off + ks * 32);
            ldm_x4(al, smb + AQ_L + qa_off + ks * 32);
            #pragma unroll
            for (int jp = 0; jp < 4; ++jp) {
                uint32_t r[4];
                ldm_x4(r, sb + kb_off + (jp * 16 * AST + ks * 16) * 2);
                kfh[2*jp][0] = r[0]; kfh[2*jp][1] = r[1];
                kfh[2*jp+1][0] = r[2]; kfh[2*jp+1][1] = r[3];
                ldm_x4(r, sb + ATILE + kb_off + (jp * 16 * AST + ks * 16) * 2);
                kfl[2*jp][0] = r[0]; kfl[2*jp][1] = r[1];
                kfl[2*jp+1][0] = r[2]; kfl[2*jp+1][1] = r[3];
            }
            #pragma unroll
            for (int j = 0; j < 8; ++j) mma_bf16(sacc[j], ah, kfh[j]);
            #pragma unroll
            for (int j = 0; j < 8; ++j) mma_bf16(sacc[j], al, kfh[j]);
            #pragma unroll
            for (int j = 0; j < 8; ++j) mma_bf16(sacc[j], ah, kfl[j]);
        }

        // ---- causal mask (only diagonal tile) ----
        if (kt == qt) {
            #pragma unroll
            for (int j = 0; j < 8; ++j) {
                const int c0 = kt * 64 + j * 8 + (lane & 3) * 2;
                if (c0     > qrow0) sacc[j][0] = -1e30f;
                if (c0 + 1 > qrow0) sacc[j][1] = -1e30f;
                if (c0     > qrow1) sacc[j][2] = -1e30f;
                if (c0 + 1 > qrow1) sacc[j][3] = -1e30f;
            }
        }

        // ---- online softmax ----
        float mx0 = -1e30f, mx1 = -1e30f;
        #pragma unroll
        for (int j = 0; j < 8; ++j) {
            mx0 = fmaxf(mx0, fmaxf(sacc[j][0], sacc[j][1]));
            mx1 = fmaxf(mx1, fmaxf(sacc[j][2], sacc[j][3]));
        }
        #pragma unroll
        for (int o = 1; o < 4; o <<= 1) {
            mx0 = fmaxf(mx0, __shfl_xor_sync(0xffffffffu, mx0, o));
            mx1 = fmaxf(mx1, __shfl_xor_sync(0xffffffffu, mx1, o));
        }
        const float mn0 = fmaxf(m0, mx0), mn1 = fmaxf(m1, mx1);
        const float e0 = __expf(m0 - mn0), e1 = __expf(m1 - mn1);
        m0 = mn0; m1 = mn1;
        float rs0 = 0.f, rs1 = 0.f;
        #pragma unroll
        for (int j = 0; j < 8; ++j) {
            sacc[j][0] = __expf(sacc[j][0] - mn0); rs0 += sacc[j][0];
            sacc[j][1] = __expf(sacc[j][1] - mn0); rs0 += sacc[j][1];
            sacc[j][2] = __expf(sacc[j][2] - mn1); rs1 += sacc[j][2];
            sacc[j][3] = __expf(sacc[j][3] - mn1); rs1 += sacc[j][3];
        }
        #pragma unroll
        for (int o = 1; o < 4; o <<= 1) {
            rs0 += __shfl_xor_sync(0xffffffffu, rs0, o);
            rs1 += __shfl_xor_sync(0xffffffffu, rs1, o);
        }
        l0 = l0 * e0 + rs0;
        l1 = l1 * e1 + rs1;
        #pragma unroll
        for (int t = 0; t < 16; t++) {
            oacc[t][0] *= e0; oacc[t][1] *= e0;
            oacc[t][2] *= e1; oacc[t][3] *= e1;
        }

        // ---- O += P V (3-pass hi/lo) ----
        #pragma unroll
        for (int c = 0; c < 4; ++c) {
            uint32_t pah[4], pal[4];
            packhl(sacc[2*c][0],   sacc[2*c][1],   pah[0], pal[0]);
            packhl(sacc[2*c][2],   sacc[2*c][3],   pah[1], pal[1]);
            packhl(sacc[2*c+1][0], sacc[2*c+1][1], pah[2], pal[2]);
            packhl(sacc[2*c+1][2], sacc[2*c+1][3], pah[3], pal[3]);
            #pragma unroll
            for (int tp = 0; tp < 8; ++tp) {
                uint32_t rvh[4], rvl[4];
                ldm_x4_t(rvh, sb + 2 * ATILE + vb_off + (c * 16 * AST + tp * 16) * 2);
                ldm_x4_t(rvl, sb + 3 * ATILE + vb_off + (c * 16 * AST + tp * 16) * 2);
                mma_bf16(oacc[2*tp],   pah, &rvh[0]);
                mma_bf16(oacc[2*tp],   pal, &rvh[0]);
                mma_bf16(oacc[2*tp],   pah, &rvl[0]);
                mma_bf16(oacc[2*tp+1], pah, &rvh[2]);
                mma_bf16(oacc[2*tp+1], pal, &rvh[2]);
                mma_bf16(oacc[2*tp+1], pah, &rvl[2]);
            }
        }
        __syncthreads();
    }

    // ---- epilogue ----
    const float inv0 = 1.0f / l0, inv1 = 1.0f / l1;
    const size_t ob0 = ((size_t)b * SS + qrow0) * HID + h * HD;
    const size_t ob1 = ((size_t)b * SS + qrow1) * HID + h * HD;
    #pragma unroll
    for (int t = 0; t < 16; ++t) {
        const int d = t * 8 + (lane & 3) * 2;
        uint32_t hi, lo;
        packhl(oacc[t][0] * inv0, oacc[t][1] * inv0, hi, lo);
        *(uint32_t*)(ctxh + ob0 + d) = hi;
        *(uint32_t*)(ctxl + ob0 + d) = lo;
        packhl(oacc[t][2] * inv1, oacc[t][3] * inv1, hi, lo);
        *(uint32_t*)(ctxh + ob1 + d) = hi;
        *(uint32_t*)(ctxl + ob1 + d) = lo;
    }
}

// ---------------- launch ----------------
extern "C" void kernel_launch(void* const* d_in, const int* in_sizes, int n_in,
                              void* d_out, int out_size) {
    const float* hid   = (const float*)d_in[0];
    const float* ln1g  = (const float*)d_in[1];
    const float* ln1b  = (const float*)d_in[2];
    const float* ln2g  = (const float*)d_in[3];
    const float* ln2b  = (const float*)d_in[4];
    const float* Wqkv  = (const float*)d_in[5];
    const float* bqkv  = (const float*)d_in[6];
    const float* Wo    = (const float*)d_in[7];
    const float* bo    = (const float*)d_in[8];
    const float* Wfc   = (const float*)d_in[9];
    const float* bfc   = (const float*)d_in[10];
    const float* Wproj = (const float*)d_in[11];
    const float* bproj = (const float*)d_in[12];
    float* out = (float*)d_out;

    float *qkv, *att, *rope;
    bf16 *ln1h, *ln1l, *ln2h, *ln2l, *ctxh, *ctxl, *fch, *fcl;
    bf16 *Qh, *Ql, *Kh, *Kl, *Vh, *Vl;
    bf16 *wqkvh, *wqkvl, *woh, *wol, *wfch, *wfcl, *wprojh, *wprojl;
    cudaGetSymbolAddress((void**)&qkv, g_qkv);
    cudaGetSymbolAddress((void**)&att, g_att);
    cudaGetSymbolAddress((void**)&rope, g_rope);
    cudaGetSymbolAddress((void**)&ln1h, g_ln1h);
    cudaGetSymbolAddress((void**)&ln1l, g_ln1l);
    cudaGetSymbolAddress((void**)&ln2h, g_ln2h);
    cudaGetSymbolAddress((void**)&ln2l, g_ln2l);
    cudaGetSymbolAddress((void**)&ctxh, g_ctxh);
    cudaGetSymbolAddress((void**)&ctxl, g_ctxl);
    cudaGetSymbolAddress((void**)&fch, g_fch);
    cudaGetSymbolAddress((void**)&fcl, g_fcl);
    cudaGetSymbolAddress((void**)&Qh, g_Qh);
    cudaGetSymbolAddress((void**)&Ql, g_Ql);
    cudaGetSymbolAddress((void**)&Kh, g_Kh);
    cudaGetSymbolAddress((void**)&Kl, g_Kl);
    cudaGetSymbolAddress((void**)&Vh, g_Vh);
    cudaGetSymbolAddress((void**)&Vl, g_Vl);
    cudaGetSymbolAddress((void**)&wqkvh, g_wqkvh);
    cudaGetSymbolAddress((void**)&wqkvl, g_wqkvl);
    cudaGetSymbolAddress((void**)&woh, g_woh);
    cudaGetSymbolAddress((void**)&wol, g_wol);
    cudaGetSymbolAddress((void**)&wfch, g_wfch);
    cudaGetSymbolAddress((void**)&wfcl, g_wfcl);
    cudaGetSymbolAddress((void**)&wprojh, g_wprojh);
    cudaGetSymbolAddress((void**)&wprojl, g_wprojl);

    cudaFuncSetAttribute(mma_gemm<0>, cudaFuncAttributeMaxDynamicSharedMemorySize, G_SMEM);
    cudaFuncSetAttribute(mma_gemm<1>, cudaFuncAttributeMaxDynamicSharedMemorySize, G_SMEM);
    cudaFuncSetAttribute(mma_gemm<2>, cudaFuncAttributeMaxDynamicSharedMemorySize, G_SMEM);
    cudaFuncSetAttribute(attn_mma_kernel, cudaFuncAttributeMaxDynamicSharedMemorySize, A_SMEM);

    // weight conversions + rope table
    wconv_kernel<<<dim3(3 * HID / 32, HID / 32), dim3(32, 8)>>>(Wqkv, wqkvh, wqkvl, HID, 3 * HID);
    wconv_kernel<<<dim3(HID / 32, HID / 32),     dim3(32, 8)>>>(Wo,   woh,   wol,   HID, HID);
    wconv_kernel<<<dim3(FF / 32, HID / 32),      dim3(32, 8)>>>(Wfc,  wfch,  wfcl,  HID, FF);
    wconv_kernel<<<dim3(HID / 32, FF / 32),      dim3(32, 8)>>>(Wproj, wprojh, wprojl, FF, HID);
    rope_tab_kernel<<<SS * 16 / 256, 256>>>(rope);

    // 1. LN1 + LN2 fused -> bf16 hi/lo
    ln_kernel<<<NTOK, 256>>>(hid, ln1g, ln1b, ln2g, ln2b, ln1h, ln1l, ln2h, ln2l);

    // 2. QKV = ln1 @ W_qkv + b_qkv -> fp32
    mma_gemm<0><<<dim3(NTOK / 128, 3 * HID / 128), 256, G_SMEM>>>(
        ln1h, ln1l, wqkvh, wqkvl, bqkv, nullptr, nullptr, qkv, nullptr, nullptr,
        3 * HID, HID);

    // 3. RoPE + transpose + scale + split -> Q/K/V head-major bf16 hi/lo
    qkv2attn_kernel<<<NTOK, 512>>>(qkv, rope, Qh, Ql, Kh, Kl, Vh, Vl);

    // 4. causal attention (mma.sync) -> ctx bf16 hi/lo (token-major)
    attn_mma_kernel<<<dim3(SS / 64, BB * HH), 128, A_SMEM>>>(
        Qh, Ql, Kh, Kl, Vh, Vl, ctxh, ctxl);

    // 5. attn_out = ctx @ W_o + b_o -> fp32
    mma_gemm<0><<<dim3(NTOK / 128, HID / 128), 256, G_SMEM>>>(
        ctxh, ctxl, woh, wol, bo, nullptr, nullptr, att, nullptr, nullptr,
        HID, HID);

    // 6. fc = gelu(ln2 @ W_fc + b_fc) -> bf16 hi/lo
    mma_gemm<1><<<dim3(NTOK / 128, FF / 128), 256, G_SMEM>>>(
        ln2h, ln2l, wfch, wfcl, bfc, nullptr, nullptr, nullptr, fch, fcl,
        FF, HID);

    // 7. out = fc @ W_proj + b_proj + attn_out + hidden
    mma_gemm<2><<<dim3(NTOK / 128, HID / 128), 256, G_SMEM>>>(
        fch, fcl, wprojh, wprojl, bproj, att, hid, out, nullptr, nullptr,
        HID, FF);
}

// round 5
// speedup vs baseline: 4.9467x; 1.1251x over previous
#include <cuda_runtime.h>
#include <cuda_bf16.h>
#include <cstdint>

// Problem constants
#define BB 2
#define SS 2048
#define HH 16
#define HD 128
#define HID 2048
#define FF 8192
#define NTOK 4096

typedef __nv_bfloat16 bf16;

// ---------------- scratch (device globals; no allocation allowed) ----------
__device__ float g_qkv[(size_t)NTOK * 3 * HID];
__device__ float g_att[(size_t)NTOK * HID];
__device__ float g_rope[SS * 16 * 2];
__device__ bf16 g_ln1h[(size_t)NTOK * HID];
__device__ bf16 g_ln1l[(size_t)NTOK * HID];
__device__ bf16 g_ln2h[(size_t)NTOK * HID];
__device__ bf16 g_ln2l[(size_t)NTOK * HID];
__device__ bf16 g_ctxh[(size_t)NTOK * HID];
__device__ bf16 g_ctxl[(size_t)NTOK * HID];
__device__ bf16 g_fch[(size_t)NTOK * FF];
__device__ bf16 g_fcl[(size_t)NTOK * FF];
__device__ bf16 g_Qh[(size_t)NTOK * HID];
__device__ bf16 g_Ql[(size_t)NTOK * HID];
__device__ bf16 g_Kh[(size_t)NTOK * HID];
__device__ bf16 g_Kl[(size_t)NTOK * HID];
__device__ bf16 g_Vh[(size_t)NTOK * HID];
__device__ bf16 g_Vl[(size_t)NTOK * HID];
__device__ bf16 g_wqkvh[(size_t)3 * HID * HID];
__device__ bf16 g_wqkvl[(size_t)3 * HID * HID];
__device__ bf16 g_woh[(size_t)HID * HID];
__device__ bf16 g_wol[(size_t)HID * HID];
__device__ bf16 g_wfch[(size_t)FF * HID];
__device__ bf16 g_wfcl[(size_t)FF * HID];
__device__ bf16 g_wprojh[(size_t)HID * FF];
__device__ bf16 g_wprojl[(size_t)HID * FF];

// ---------------- helpers ----------------
__device__ __forceinline__ uint32_t smem_u32(const void* p) {
    uint32_t a;
    asm("{ .reg .u64 t; cvta.to.shared.u64 t, %1; cvt.u32.u64 %0, t; }" : "=r"(a) : "l"(p));
    return a;
}
#define CP16(dst, src) \
    asm volatile("cp.async.cg.shared.global [%0], [%1], 16;" :: "r"(dst), "l"(src) : "memory")
#define CP_COMMIT() asm volatile("cp.async.commit_group;" ::: "memory")
#define CP_WAIT1()  asm volatile("cp.async.wait_group 1;" ::: "memory")
#define CP_WAIT0()  asm volatile("cp.async.wait_group 0;" ::: "memory")

__device__ __forceinline__ void ldm_x4(uint32_t* r, uint32_t addr) {
    asm volatile("ldmatrix.sync.aligned.m8n8.x4.shared.b16 {%0,%1,%2,%3}, [%4];"
                 : "=r"(r[0]), "=r"(r[1]), "=r"(r[2]), "=r"(r[3]) : "r"(addr));
}
__device__ __forceinline__ void ldm_x4_t(uint32_t* r, uint32_t addr) {
    asm volatile("ldmatrix.sync.aligned.m8n8.x4.trans.shared.b16 {%0,%1,%2,%3}, [%4];"
                 : "=r"(r[0]), "=r"(r[1]), "=r"(r[2]), "=r"(r[3]) : "r"(addr));
}
__device__ __forceinline__ void mma_bf16(float* c, const uint32_t* a, const uint32_t* b) {
    asm volatile("mma.sync.aligned.m16n8k16.row.col.f32.bf16.bf16.f32 "
                 "{%0,%1,%2,%3},{%4,%5,%6,%7},{%8,%9},{%0,%1,%2,%3};"
                 : "+f"(c[0]), "+f"(c[1]), "+f"(c[2]), "+f"(c[3])
                 : "r"(a[0]), "r"(a[1]), "r"(a[2]), "r"(a[3]), "r"(b[0]), "r"(b[1]));
}
__device__ __forceinline__ void split_bf16(float v, bf16& h, bf16& l) {
    h = __float2bfloat16(v);
    l = __float2bfloat16(v - __bfloat162float(h));
}
__device__ __forceinline__ void packhl(float a, float b, uint32_t& hi, uint32_t& lo) {
    __nv_bfloat162 hv, lv;
    split_bf16(a, hv.x, lv.x);
    split_bf16(b, hv.y, lv.y);
    hi = *(uint32_t*)&hv;
    lo = *(uint32_t*)&lv;
}
__device__ __forceinline__ float gelu_exact(float v) {
    return 0.5f * v * (1.0f + erff(v * 0.70710678118654752f));
}

// ---------------- fused double layernorm -> bf16 hi/lo ----------------
__global__ void ln_kernel(const float* __restrict__ x,
                          const float* __restrict__ g1, const float* __restrict__ b1,
                          const float* __restrict__ g2, const float* __restrict__ b2,
                          bf16* __restrict__ o1h, bf16* __restrict__ o1l,
                          bf16* __restrict__ o2h, bf16* __restrict__ o2l) {
    __shared__ float redS[8];
    __shared__ float redQ[8];
    const int row = blockIdx.x;
    const float* xr = x + (size_t)row * HID;
    const int t = threadIdx.x;
    float4 a = *(const float4*)(xr + t * 8);
    float4 b = *(const float4*)(xr + t * 8 + 4);
    float s  = a.x + a.y + a.z + a.w + b.x + b.y + b.z + b.w;
    float ss = a.x*a.x + a.y*a.y + a.z*a.z + a.w*a.w
             + b.x*b.x + b.y*b.y + b.z*b.z + b.w*b.w;
    #pragma unroll
    for (int o = 16; o; o >>= 1) {
        s  += __shfl_xor_sync(0xffffffffu, s,  o);
        ss += __shfl_xor_sync(0xffffffffu, ss, o);
    }
    if ((t & 31) == 0) { redS[t >> 5] = s; redQ[t >> 5] = ss; }
    __syncthreads();
    s = 0.f; ss = 0.f;
    #pragma unroll
    for (int i = 0; i < 8; i++) { s += redS[i]; ss += redQ[i]; }
    const float mu  = s * (1.0f / HID);
    const float var = ss * (1.0f / HID) - mu * mu;
    const float rs  = rsqrtf(var + 1e-5f);

    float vals[8] = {a.x,a.y,a.z,a.w,b.x,b.y,b.z,b.w};
    __align__(16) bf16 h1[8], l1[8], h2[8], l2[8];
    #pragma unroll
    for (int q = 0; q < 8; q++) {
        const int col = t * 8 + q;
        const float xn = (vals[q] - mu) * rs;
        split_bf16(xn * g1[col] + b1[col], h1[q], l1[q]);
        split_bf16(xn * g2[col] + b2[col], h2[q], l2[q]);
    }
    const size_t off = (size_t)row * HID + t * 8;
    *(uint4*)(o1h + off) = *(uint4*)h1;
    *(uint4*)(o1l + off) = *(uint4*)l1;
    *(uint4*)(o2h + off) = *(uint4*)h2;
    *(uint4*)(o2l + off) = *(uint4*)l2;
}

// ---------------- weight convert + transpose: W[K][N] -> T{h,l}[N][K] ------
__global__ void wconv_kernel(const float* __restrict__ W, bf16* __restrict__ Th,
                             bf16* __restrict__ Tl, int K, int N) {
    __shared__ float tile[32][33];
    const int n0 = blockIdx.x * 32, k0 = blockIdx.y * 32;
    const int tx = threadIdx.x, ty = threadIdx.y;  // 32 x 8
    #pragma unroll
    for (int i = 0; i < 4; i++)
        tile[ty + 8 * i][tx] = W[(size_t)(k0 + ty + 8 * i) * N + n0 + tx];
    __syncthreads();
    #pragma unroll
    for (int i = 0; i < 4; i++) {
        const float v = tile[tx][ty + 8 * i];
        const size_t idx = (size_t)(n0 + ty + 8 * i) * K + k0 + tx;
        bf16 h, l;
        split_bf16(v, h, l);
        Th[idx] = h; Tl[idx] = l;
    }
}

// ---------------- RoPE cos/sin table ----------------
__global__ void rope_tab_kernel(float* __restrict__ tab) {
    const int i = blockIdx.x * 256 + threadIdx.x;
    const int s = i >> 4, fi = i & 15;
    const float inv = powf(10000.0f, -(float)fi * (1.0f / 16.0f));
    float sn, cs;
    sincosf((float)s * inv, &sn, &cs);
    tab[i * 2]     = cs;
    tab[i * 2 + 1] = sn;
}

// ---------------- qkv fp32 -> RoPE + head-major bf16 hi/lo ----------------
__global__ void qkv2attn_kernel(const float* __restrict__ qkv,
                                const float* __restrict__ tab,
                                bf16* __restrict__ Qh, bf16* __restrict__ Ql,
                                bf16* __restrict__ Kh, bf16* __restrict__ Kl,
                                bf16* __restrict__ Vh, bf16* __restrict__ Vl) {
    const int t = blockIdx.x;
    const int b = t >> 11, s = t & (SS - 1);
    const int tid = threadIdx.x;       // 512
    const int h = tid >> 5;
    const int d0 = (tid & 31) * 4;
    const float* base = qkv + (size_t)t * (3 * HID) + h * (3 * HD);

    float4 qv = *(const float4*)(base + d0);
    float4 kv = *(const float4*)(base + HD + d0);
    float4 vv = *(const float4*)(base + 2 * HD + d0);

    if (d0 < 32) {
        const bool first = d0 < 16;
        const int pd = first ? d0 + 16 : d0 - 16;
        const float4 qp = *(const float4*)(base + pd);
        const float4 kp = *(const float4*)(base + HD + pd);
        float qa[4] = {qv.x, qv.y, qv.z, qv.w};
        float ka[4] = {kv.x, kv.y, kv.z, kv.w};
        const float qpp[4] = {qp.x, qp.y, qp.z, qp.w};
        const float kpp[4] = {kp.x, kp.y, kp.z, kp.w};
        #pragma unroll
        for (int i = 0; i < 4; i++) {
            const int fi = (d0 + i) & 15;
            const float cs = tab[(s * 16 + fi) * 2];
            const float sn = tab[(s * 16 + fi) * 2 + 1];
            if (first) {
                qa[i] = qa[i] * cs - qpp[i] * sn;
                ka[i] = ka[i] * cs - kpp[i] * sn;
            } else {
                qa[i] = qa[i] * cs + qpp[i] * sn;
                ka[i] = ka[i] * cs + kpp[i] * sn;
            }
        }
        qv = make_float4(qa[0], qa[1], qa[2], qa[3]);
        kv = make_float4(ka[0], ka[1], ka[2], ka[3]);
    }
    const float sc = 0.08838834764831845f;
    qv.x *= sc; qv.y *= sc; qv.z *= sc; qv.w *= sc;

    const size_t off = ((size_t)(b * HH + h) * SS + s) * HD + d0;
    __align__(8) bf16 hh[4], ll[4];
    split_bf16(qv.x, hh[0], ll[0]); split_bf16(qv.y, hh[1], ll[1]);
    split_bf16(qv.z, hh[2], ll[2]); split_bf16(qv.w, hh[3], ll[3]);
    *(uint2*)(Qh + off) = *(uint2*)hh; *(uint2*)(Ql + off) = *(uint2*)ll;
    split_bf16(kv.x, hh[0], ll[0]); split_bf16(kv.y, hh[1], ll[1]);
    split_bf16(kv.z, hh[2], ll[2]); split_bf16(kv.w, hh[3], ll[3]);
    *(uint2*)(Kh + off) = *(uint2*)hh; *(uint2*)(Kl + off) = *(uint2*)ll;
    split_bf16(vv.x, hh[0], ll[0]); split_bf16(vv.y, hh[1], ll[1]);
    split_bf16(vv.z, hh[2], ll[2]); split_bf16(vv.w, hh[3], ll[3]);
    *(uint2*)(Vh + off) = *(uint2*)hh; *(uint2*)(Vl + off) = *(uint2*)ll;
}

// ---------------- mma.sync bf16-split GEMM, BK=64 ----------------
// C[M,N] = A[M,K] * B^T (B stored as T[N][K]). CTA tile 128x128, BK=64.
// smem per stage: 4 arrays x [128][72] bf16 = 73728 B; 2 stages = 147456 B.
#define ROWP   72
#define ARR_B  18432u
#define STG_B  73728u
#define G_SMEM (2u * STG_B)

template <int EPI>  // 0: +bias->f32   1: gelu(+bias)->bf16 hi/lo   2: +bias+add1+add2->f32
__global__ void __launch_bounds__(256, 1) mma_gemm(
    const bf16* __restrict__ Ah, const bf16* __restrict__ Al,
    const bf16* __restrict__ Bh, const bf16* __restrict__ Bl,
    const float* __restrict__ bias,
    const float* __restrict__ add1, const float* __restrict__ add2,
    float* __restrict__ Cf, bf16* __restrict__ Ch, bf16* __restrict__ Cl,
    int N, int K) {
    extern __shared__ char sm[];
    const uint32_t smb = smem_u32(sm);
    const int tid = threadIdx.x;
    const int lane = tid & 31;
    const int wm = (tid >> 5) & 3;
    const int wn = (tid >> 7);

    const size_t arow0 = (size_t)blockIdx.x * 128;
    const size_t brow0 = (size_t)blockIdx.y * 128;
    const bf16* pa_h = Ah + arow0 * K;
    const bf16* pa_l = Al + arow0 * K;
    const bf16* pb_h = Bh + brow0 * K;
    const bf16* pb_l = Bl + brow0 * K;
    const int nch = K >> 6;

    const uint32_t aoff = ((wm * 32 + (lane & 15)) * ROWP + (lane >> 4) * 8) * 2;
    const uint32_t boff = ((wn * 64 + (lane & 7) + ((lane >> 4) & 1) * 8) * ROWP
                           + ((lane >> 3) & 1) * 8) * 2;

    float acc[2][8][4];
    #pragma unroll
    for (int m = 0; m < 2; m++)
        #pragma unroll
        for (int n = 0; n < 8; n++)
            #pragma unroll
            for (int q = 0; q < 4; q++) acc[m][n][q] = 0.f;

    // stage loader: per array, 1024 16B-chunks (128 rows x 8), 4 per thread
    auto load_stage = [&](int stg, int k0) {
        const uint32_t sb = smb + (uint32_t)stg * STG_B;
        const bf16* srcs[4] = {pa_h, pa_l, pb_h, pb_l};
        #pragma unroll
        for (int a4 = 0; a4 < 4; ++a4) {
            const bf16* sp = srcs[a4];
            const uint32_t db = sb + a4 * ARR_B;
            #pragma unroll
            for (int i = 0; i < 4; ++i) {
                const int id = tid + i * 256;
                const int row = id >> 3, cc = id & 7;
                CP16(db + (uint32_t)(row * ROWP + cc * 8) * 2,
                     sp + (size_t)row * K + k0 + cc * 8);
            }
        }
    };

    load_stage(0, 0);
    CP_COMMIT();

    for (int c = 0; c < nch; ++c) {
        if (c + 1 < nch) {
            load_stage((c + 1) & 1, (c + 1) << 6);
            CP_COMMIT();
            CP_WAIT1();
        } else {
            CP_WAIT0();
        }
        __syncthreads();

        const uint32_t sb = smb + (uint32_t)(c & 1) * STG_B;
        #pragma unroll
        for (int ks = 0; ks < 4; ++ks) {
            const uint32_t kb = ks * 32;       // 16 elems * 2B
            uint32_t ah[2][4], xf[2][4], bh[4][4], bl[4][4];
            ldm_x4(ah[0], sb + aoff + kb);
            ldm_x4(ah[1], sb + aoff + kb + 16 * ROWP * 2);
            #pragma unroll
            for (int t2 = 0; t2 < 4; ++t2)
                ldm_x4(bh[t2], sb + 2 * ARR_B + boff + kb + t2 * 16 * ROWP * 2);
            #pragma unroll
            for (int m = 0; m < 2; ++m)
                #pragma unroll
                for (int n = 0; n < 8; ++n)
                    mma_bf16(acc[m][n], ah[m], &bh[n >> 1][(n & 1) * 2]);
            ldm_x4(xf[0], sb + ARR_B + aoff + kb);
            ldm_x4(xf[1], sb + ARR_B + aoff + kb + 16 * ROWP * 2);
            #pragma unroll
            for (int m = 0; m < 2; ++m)
                #pragma unroll
                for (int n = 0; n < 8; ++n)
                    mma_bf16(acc[m][n], xf[m], &bh[n >> 1][(n & 1) * 2]);
            #pragma unroll
            for (int t2 = 0; t2 < 4; ++t2)
                ldm_x4(bl[t2], sb + 3 * ARR_B + boff + kb + t2 * 16 * ROWP * 2);
            #pragma unroll
            for (int m = 0; m < 2; ++m)
                #pragma unroll
                for (int n = 0; n < 8; ++n)
                    mma_bf16(acc[m][n], ah[m], &bl[n >> 1][(n & 1) * 2]);
        }
        __syncthreads();
    }

    const int row_base = blockIdx.x * 128 + wm * 32;
    const int col_base = blockIdx.y * 128 + wn * 64;
    #pragma unroll
    for (int m = 0; m < 2; ++m) {
        const int r0 = row_base + m * 16 + (lane >> 2);
        #pragma unroll
        for (int n = 0; n < 8; ++n) {
            const int cc = col_base + n * 8 + (lane & 3) * 2;
            const float b0 = bias[cc], b1 = bias[cc + 1];
            float v0 = acc[m][n][0] + b0, v1 = acc[m][n][1] + b1;
            float v2 = acc[m][n][2] + b0, v3 = acc[m][n][3] + b1;
            const size_t off0 = (size_t)r0 * N + cc;
            const size_t off1 = (size_t)(r0 + 8) * N + cc;
            if (EPI == 1) {
                bf16 h, l;
                __nv_bfloat162 hv, lv;
                split_bf16(gelu_exact(v0), h, l); hv.x = h; lv.x = l;
                split_bf16(gelu_exact(v1), h, l); hv.y = h; lv.y = l;
                *(__nv_bfloat162*)(Ch + off0) = hv;
                *(__nv_bfloat162*)(Cl + off0) = lv;
                split_bf16(gelu_exact(v2), h, l); hv.x = h; lv.x = l;
                split_bf16(gelu_exact(v3), h, l); hv.y = h; lv.y = l;
                *(__nv_bfloat162*)(Ch + off1) = hv;
                *(__nv_bfloat162*)(Cl + off1) = lv;
            } else {
                if (EPI == 2) {
                    const float2 x0 = *(const float2*)(add1 + off0);
                    const float2 y0 = *(const float2*)(add2 + off0);
                    const float2 x1 = *(const float2*)(add1 + off1);
                    const float2 y1 = *(const float2*)(add2 + off1);
                    v0 += x0.x + y0.x; v1 += x0.y + y0.y;
                    v2 += x1.x + y1.x; v3 += x1.y + y1.y;
                }
                *(float2*)(Cf + off0) = make_float2(v0, v1);
                *(float2*)(Cf + off1) = make_float2(v2, v3);
            }
        }
    }
}

// ---------------- causal flash attention via mma.sync, BQ=128 --------------
// 256 threads, 8 warps; 128 q-rows per block; K/V tiles 64 wide, double-buffered.
#define AST   136                        // smem row stride (bf16 elems)
#define ATILE (64 * AST * 2)             // 64x128 tile bytes (17408)
#define AQ_H  0
#define AQ_L  (2 * ATILE)                // Q tiles are 128 rows = 2*ATILE each
#define ASTAGE0 (4 * ATILE)
#define ASTG_B  (4 * ATILE)              // K_h,K_l,V_h,V_l
#define A_SMEM  (4 * ATILE + 2 * ASTG_B) // 208896 B

__global__ void __launch_bounds__(256, 1) attn_mma_kernel(
    const bf16* __restrict__ Qh, const bf16* __restrict__ Ql,
    const bf16* __restrict__ Kh, const bf16* __restrict__ Kl,
    const bf16* __restrict__ Vh, const bf16* __restrict__ Vl,
    bf16* __restrict__ ctxh, bf16* __restrict__ ctxl) {
    extern __shared__ char sm[];
    const uint32_t smb = smem_u32(sm);
    const int qt = gridDim.x - 1 - blockIdx.x;     // q block of 128 rows
    const int bhid = blockIdx.y;
    const int b = bhid >> 4, h = bhid & 15;
    const int tid = threadIdx.x;
    const int lane = tid & 31;
    const int w = tid >> 5;

    const size_t headbase = (size_t)bhid * SS * HD;

    auto ldq = [&]() {
        const size_t gb = headbase + (size_t)qt * 128 * HD;
        #pragma unroll
        for (int i = 0; i < 8; i++) {
            const int c = tid + i * 256;           // 2048 chunks per array
            const int row = c >> 4, ch = c & 15;
            const uint32_t so = row * (AST * 2) + ch * 16;
            const size_t go = gb + (size_t)row * HD + ch * 8;
            CP16(smb + AQ_H + so, Qh + go);
            CP16(smb + AQ_L + so, Ql + go);
        }
    };
    auto ldkv = [&](int kt, int stg) {
        const uint32_t sb = smb + ASTAGE0 + (uint32_t)stg * ASTG_B;
        const size_t gb = headbase + (size_t)kt * 64 * HD;
        #pragma unroll
        for (int i = 0; i < 4; i++) {
            const int c = tid + i * 256;           // 1024 chunks per array
            const int row = c >> 4, ch = c & 15;
            const uint32_t so = row * (AST * 2) + ch * 16;
            const size_t go = gb + (size_t)row * HD + ch * 8;
            CP16(sb + so,             Kh + go);
            CP16(sb + ATILE + so,     Kl + go);
            CP16(sb + 2 * ATILE + so, Vh + go);
            CP16(sb + 3 * ATILE + so, Vl + go);
        }
    };

    const uint32_t qa_off = ((w * 16 + (lane & 15)) * AST + (lane >> 4) * 8) * 2;
    const int lm = lane >> 3, li = lane & 7;
    const uint32_t kb_off = (((lm >> 1) * 8 + li) * AST + (lm & 1) * 8) * 2;
    const uint32_t vb_off = (((lm & 1) * 8 + li) * AST + (lm >> 1) * 8) * 2;

    float oacc[16][4];
    #pragma unroll
    for (int t = 0; t < 16; t++)
        #pragma unroll
        for (int q = 0; q < 4; q++) oacc[t][q] = 0.f;
    float m0 = -1e30f, m1 = -1e30f, l0 = 0.f, l1 = 0.f;
    const int qrow0 = qt * 128 + w * 16 + (lane >> 2);
    const int qrow1 = qrow0 + 8;
    const int nkt = 2 * qt + 2;                    // 64-wide k tiles

    ldq();
    ldkv(0, 0);
    CP_COMMIT();

    for (int kt = 0; kt < nkt; ++kt) {
        if (kt + 1 < nkt) {
            ldkv(kt + 1, (kt + 1) & 1);
            CP_COMMIT();
            CP_WAIT1();
        } else {
            CP_WAIT0();
        }
        __syncthreads();
        const uint32_t sb = smb + ASTAGE0 + (uint32_t)(kt & 1) * ASTG_B;

        // ---- S = Q K^T (3-pass hi/lo) ----
        float sacc[8][4];
        #pragma unroll
        for (int j = 0; j < 8; j++)
            #pragma unroll
            for (int q = 0; q < 4; q++) sacc[j][q] = 0.f;

        #pragma unroll
        for (int ks = 0; ks < 8; ++ks) {
            uint32_t ah[4], al[4], kfh[8][2], kfl[8][2];
            ldm_x4(ah, smb + AQ_H + qa_off + ks * 32);
            ldm_x4(al, smb + AQ_L + qa_off + ks * 32);
            #pragma unroll
            for (int jp = 0; jp < 4; ++jp) {
                uint32_t r[4];
                ldm_x4(r, sb + kb_off + (jp * 16 * AST + ks * 16) * 2);
                kfh[2*jp][0] = r[0]; kfh[2*jp][1] = r[1];
                kfh[2*jp+1][0] = r[2]; kfh[2*jp+1][1] = r[3];
                ldm_x4(r, sb + ATILE + kb_off + (jp * 16 * AST + ks * 16) * 2);
                kfl[2*jp][0] = r[0]; kfl[2*jp][1] = r[1];
                kfl[2*jp+1][0] = r[2]; kfl[2*jp+1][1] = r[3];
            }
            #pragma unroll
            for (int j = 0; j < 8; ++j) mma_bf16(sacc[j], ah, kfh[j]);
            #pragma unroll
            for (int j = 0; j < 8; ++j) mma_bf16(sacc[j], al, kfh[j]);
            #pragma unroll
            for (int j = 0; j < 8; ++j) mma_bf16(sacc[j], ah, kfl[j]);
        }

        // ---- causal mask (last two k-tiles of this q block) ----
        if (kt >= 2 * qt) {
            #pragma unroll
            for (int j = 0; j < 8; ++j) {
                const int c0 = kt * 64 + j * 8 + (lane & 3) * 2;
                if (c0     > qrow0) sacc[j][0] = -1e30f;
                if (c0 + 1 > qrow0) sacc[j][1] = -1e30f;
                if (c0     > qrow1) sacc[j][2] = -1e30f;
                if (c0 + 1 > qrow1) sacc[j][3] = -1e30f;
            }
        }

        // ---- online softmax ----
        float mx0 = -1e30f, mx1 = -1e30f;
        #pragma unroll
        for (int j = 0; j < 8; ++j) {
            mx0 = fmaxf(mx0, fmaxf(sacc[j][0], sacc[j][1]));
            mx1 = fmaxf(mx1, fmaxf(sacc[j][2], sacc[j][3]));
        }
        #pragma unroll
        for (int o = 1; o < 4; o <<= 1) {
            mx0 = fmaxf(mx0, __shfl_xor_sync(0xffffffffu, mx0, o));
            mx1 = fmaxf(mx1, __shfl_xor_sync(0xffffffffu, mx1, o));
        }
        const float mn0 = fmaxf(m0, mx0), mn1 = fmaxf(m1, mx1);
        const float e0 = __expf(m0 - mn0), e1 = __expf(m1 - mn1);
        m0 = mn0; m1 = mn1;
        float rs0 = 0.f, rs1 = 0.f;
        #pragma unroll
        for (int j = 0; j < 8; ++j) {
            sacc[j][0] = __expf(sacc[j][0] - mn0); rs0 += sacc[j][0];
            sacc[j][1] = __expf(sacc[j][1] - mn0); rs0 += sacc[j][1];
            sacc[j][2] = __expf(sacc[j][2] - mn1); rs1 += sacc[j][2];
            sacc[j][3] = __expf(sacc[j][3] - mn1); rs1 += sacc[j][3];
        }
        #pragma unroll
        for (int o = 1; o < 4; o <<= 1) {
            rs0 += __shfl_xor_sync(0xffffffffu, rs0, o);
            rs1 += __shfl_xor_sync(0xffffffffu, rs1, o);
        }
        l0 = l0 * e0 + rs0;
        l1 = l1 * e1 + rs1;
        #pragma unroll
        for (int t = 0; t < 16; t++) {
            oacc[t][0] *= e0; oacc[t][1] *= e0;
            oacc[t][2] *= e1; oacc[t][3] *= e1;
        }

        // ---- O += P V (3-pass hi/lo) ----
        #pragma unroll
        for (int c = 0; c < 4; ++c) {
            uint32_t pah[4], pal[4];
            packhl(sacc[2*c][0],   sacc[2*c][1],   pah[0], pal[0]);
            packhl(sacc[2*c][2],   sacc[2*c][3],   pah[1], pal[1]);
            packhl(sacc[2*c+1][0], sacc[2*c+1][1], pah[2], pal[2]);
            packhl(sacc[2*c+1][2], sacc[2*c+1][3], pah[3], pal[3]);
            #pragma unroll
            for (int tp = 0; tp < 8; ++tp) {
                uint32_t rvh[4], rvl[4];
                ldm_x4_t(rvh, sb + 2 * ATILE + vb_off + (c * 16 * AST + tp * 16) * 2);
                ldm_x4_t(rvl, sb + 3 * ATILE + vb_off + (c * 16 * AST + tp * 16) * 2);
                mma_bf16(oacc[2*tp],   pah, &rvh[0]);
                mma_bf16(oacc[2*tp],   pal, &rvh[0]);
                mma_bf16(oacc[2*tp],   pah, &rvl[0]);
                mma_bf16(oacc[2*tp+1], pah, &rvh[2]);
                mma_bf16(oacc[2*tp+1], pal, &rvh[2]);
                mma_bf16(oacc[2*tp+1], pah, &rvl[2]);
            }
        }
        __syncthreads();
    }

    // ---- epilogue ----
    const float inv0 = 1.0f / l0, inv1 = 1.0f / l1;
    const size_t ob0 = ((size_t)b * SS + qrow0) * HID + h * HD;
    const size_t ob1 = ((size_t)b * SS + qrow1) * HID + h * HD;
    #pragma unroll
    for (int t = 0; t < 16; ++t) {
        const int d = t * 8 + (lane & 3) * 2;
        uint32_t hi, lo;
        packhl(oacc[t][0] * inv0, oacc[t][1] * inv0, hi, lo);
        *(uint32_t*)(ctxh + ob0 + d) = hi;
        *(uint32_t*)(ctxl + ob0 + d) = lo;
        packhl(oacc[t][2] * inv1, oacc[t][3] * inv1, hi, lo);
        *(uint32_t*)(ctxh + ob1 + d) = hi;
        *(uint32_t*)(ctxl + ob1 + d) = lo;
    }
}

// ---------------- launch ----------------
extern "C" void kernel_launch(void* const* d_in, const int* in_sizes, int n_in,
                              void* d_out, int out_size) {
    const float* hid   = (const float*)d_in[0];
    const float* ln1g  = (const float*)d_in[1];
    const float* ln1b  = (const float*)d_in[2];
    const float* ln2g  = (const float*)d_in[3];
    const float* ln2b  = (const float*)d_in[4];
    const float* Wqkv  = (const float*)d_in[5];
    const float* bqkv  = (const float*)d_in[6];
    const float* Wo    = (const float*)d_in[7];
    const float* bo    = (const float*)d_in[8];
    const float* Wfc   = (const float*)d_in[9];
    const float* bfc   = (const float*)d_in[10];
    const float* Wproj = (const float*)d_in[11];
    const float* bproj = (const float*)d_in[12];
    float* out = (float*)d_out;

    float *qkv, *att, *rope;
    bf16 *ln1h, *ln1l, *ln2h, *ln2l, *ctxh, *ctxl, *fch, *fcl;
    bf16 *Qh, *Ql, *Kh, *Kl, *Vh, *Vl;
    bf16 *wqkvh, *wqkvl, *woh, *wol, *wfch, *wfcl, *wprojh, *wprojl;
    cudaGetSymbolAddress((void**)&qkv, g_qkv);
    cudaGetSymbolAddress((void**)&att, g_att);
    cudaGetSymbolAddress((void**)&rope, g_rope);
    cudaGetSymbolAddress((void**)&ln1h, g_ln1h);
    cudaGetSymbolAddress((void**)&ln1l, g_ln1l);
    cudaGetSymbolAddress((void**)&ln2h, g_ln2h);
    cudaGetSymbolAddress((void**)&ln2l, g_ln2l);
    cudaGetSymbolAddress((void**)&ctxh, g_ctxh);
    cudaGetSymbolAddress((void**)&ctxl, g_ctxl);
    cudaGetSymbolAddress((void**)&fch, g_fch);
    cudaGetSymbolAddress((void**)&fcl, g_fcl);
    cudaGetSymbolAddress((void**)&Qh, g_Qh);
    cudaGetSymbolAddress((void**)&Ql, g_Ql);
    cudaGetSymbolAddress((void**)&Kh, g_Kh);
    cudaGetSymbolAddress((void**)&Kl, g_Kl);
    cudaGetSymbolAddress((void**)&Vh, g_Vh);
    cudaGetSymbolAddress((void**)&Vl, g_Vl);
    cudaGetSymbolAddress((void**)&wqkvh, g_wqkvh);
    cudaGetSymbolAddress((void**)&wqkvl, g_wqkvl);
    cudaGetSymbolAddress((void**)&woh, g_woh);
    cudaGetSymbolAddress((void**)&wol, g_wol);
    cudaGetSymbolAddress((void**)&wfch, g_wfch);
    cudaGetSymbolAddress((void**)&wfcl, g_wfcl);
    cudaGetSymbolAddress((void**)&wprojh, g_wprojh);
    cudaGetSymbolAddress((void**)&wprojl, g_wprojl);

    cudaFuncSetAttribute(mma_gemm<0>, cudaFuncAttributeMaxDynamicSharedMemorySize, G_SMEM);
    cudaFuncSetAttribute(mma_gemm<1>, cudaFuncAttributeMaxDynamicSharedMemorySize, G_SMEM);
    cudaFuncSetAttribute(mma_gemm<2>, cudaFuncAttributeMaxDynamicSharedMemorySize, G_SMEM);
    cudaFuncSetAttribute(attn_mma_kernel, cudaFuncAttributeMaxDynamicSharedMemorySize, A_SMEM);

    // weight conversions + rope table
    wconv_kernel<<<dim3(3 * HID / 32, HID / 32), dim3(32, 8)>>>(Wqkv, wqkvh, wqkvl, HID, 3 * HID);
    wconv_kernel<<<dim3(HID / 32, HID / 32),     dim3(32, 8)>>>(Wo,   woh,   wol,   HID, HID);
    wconv_kernel<<<dim3(FF / 32, HID / 32),      dim3(32, 8)>>>(Wfc,  wfch,  wfcl,  HID, FF);
    wconv_kernel<<<dim3(HID / 32, FF / 32),      dim3(32, 8)>>>(Wproj, wprojh, wprojl, FF, HID);
    rope_tab_kernel<<<SS * 16 / 256, 256>>>(rope);

    // 1. LN1 + LN2 fused -> bf16 hi/lo
    ln_kernel<<<NTOK, 256>>>(hid, ln1g, ln1b, ln2g, ln2b, ln1h, ln1l, ln2h, ln2l);

    // 2. QKV = ln1 @ W_qkv + b_qkv -> fp32
    mma_gemm<0><<<dim3(NTOK / 128, 3 * HID / 128), 256, G_SMEM>>>(
        ln1h, ln1l, wqkvh, wqkvl, bqkv, nullptr, nullptr, qkv, nullptr, nullptr,
        3 * HID, HID);

    // 3. RoPE + transpose + scale + split -> Q/K/V head-major bf16 hi/lo
    qkv2attn_kernel<<<NTOK, 512>>>(qkv, rope, Qh, Ql, Kh, Kl, Vh, Vl);

    // 4. causal attention (mma.sync, BQ=128) -> ctx bf16 hi/lo
    attn_mma_kernel<<<dim3(SS / 128, BB * HH), 256, A_SMEM>>>(
        Qh, Ql, Kh, Kl, Vh, Vl, ctxh, ctxl);

    // 5. attn_out = ctx @ W_o + b_o -> fp32
    mma_gemm<0><<<dim3(NTOK / 128, HID / 128), 256, G_SMEM>>>(
        ctxh, ctxl, woh, wol, bo, nullptr, nullptr, att, nullptr, nullptr,
        HID, HID);

    // 6. fc = gelu(ln2 @ W_fc + b_fc) -> bf16 hi/lo
    mma_gemm<1><<<dim3(NTOK / 128, FF / 128), 256, G_SMEM>>>(
        ln2h, ln2l, wfch, wfcl, bfc, nullptr, nullptr, nullptr, fch, fcl,
        FF, HID);

    // 7. out = fc @ W_proj + b_proj + attn_out + hidden
    mma_gemm<2><<<dim3(NTOK / 128, HID / 128), 256, G_SMEM>>>(
        fch, fcl, wprojh, wprojl, bproj, att, hid, out, nullptr, nullptr,
        HID, FF);
}

// round 6
// speedup vs baseline: 5.3012x; 1.0717x over previous
#include <cuda_runtime.h>
#include <cuda_bf16.h>
#include <cstdint>

// Problem constants
#define BB 2
#define SS 2048
#define HH 16
#define HD 128
#define HID 2048
#define FF 8192
#define NTOK 4096

typedef __nv_bfloat16 bf16;

// ---------------- scratch (device globals; no allocation allowed) ----------
__device__ float g_att[(size_t)NTOK * HID];
__device__ float g_rope[SS * 16 * 2];
__device__ bf16 g_ln1h[(size_t)NTOK * HID];
__device__ bf16 g_ln1l[(size_t)NTOK * HID];
__device__ bf16 g_ln2h[(size_t)NTOK * HID];
__device__ bf16 g_ln2l[(size_t)NTOK * HID];
__device__ bf16 g_ctxh[(size_t)NTOK * HID];
__device__ bf16 g_ctxl[(size_t)NTOK * HID];
__device__ bf16 g_fch[(size_t)NTOK * FF];
__device__ bf16 g_fcl[(size_t)NTOK * FF];
__device__ bf16 g_Qh[(size_t)NTOK * HID];
__device__ bf16 g_Ql[(size_t)NTOK * HID];
__device__ bf16 g_Kh[(size_t)NTOK * HID];
__device__ bf16 g_Kl[(size_t)NTOK * HID];
__device__ bf16 g_Vh[(size_t)NTOK * HID];
__device__ bf16 g_Vl[(size_t)NTOK * HID];
__device__ bf16 g_wqkvh[(size_t)3 * HID * HID];
__device__ bf16 g_wqkvl[(size_t)3 * HID * HID];
__device__ bf16 g_woh[(size_t)HID * HID];
__device__ bf16 g_wol[(size_t)HID * HID];
__device__ bf16 g_wfch[(size_t)FF * HID];
__device__ bf16 g_wfcl[(size_t)FF * HID];
__device__ bf16 g_wprojh[(size_t)HID * FF];
__device__ bf16 g_wprojl[(size_t)HID * FF];

// ---------------- helpers ----------------
__device__ __forceinline__ uint32_t smem_u32(const void* p) {
    uint32_t a;
    asm("{ .reg .u64 t; cvta.to.shared.u64 t, %1; cvt.u32.u64 %0, t; }" : "=r"(a) : "l"(p));
    return a;
}
#define CP16(dst, src) \
    asm volatile("cp.async.cg.shared.global [%0], [%1], 16;" :: "r"(dst), "l"(src) : "memory")
#define CP_COMMIT() asm volatile("cp.async.commit_group;" ::: "memory")
#define CP_WAIT1()  asm volatile("cp.async.wait_group 1;" ::: "memory")
#define CP_WAIT0()  asm volatile("cp.async.wait_group 0;" ::: "memory")

__device__ __forceinline__ void ldm_x4(uint32_t* r, uint32_t addr) {
    asm volatile("ldmatrix.sync.aligned.m8n8.x4.shared.b16 {%0,%1,%2,%3}, [%4];"
                 : "=r"(r[0]), "=r"(r[1]), "=r"(r[2]), "=r"(r[3]) : "r"(addr));
}
__device__ __forceinline__ void ldm_x4_t(uint32_t* r, uint32_t addr) {
    asm volatile("ldmatrix.sync.aligned.m8n8.x4.trans.shared.b16 {%0,%1,%2,%3}, [%4];"
                 : "=r"(r[0]), "=r"(r[1]), "=r"(r[2]), "=r"(r[3]) : "r"(addr));
}
__device__ __forceinline__ void mma_bf16(float* c, const uint32_t* a, const uint32_t* b) {
    asm volatile("mma.sync.aligned.m16n8k16.row.col.f32.bf16.bf16.f32 "
                 "{%0,%1,%2,%3},{%4,%5,%6,%7},{%8,%9},{%0,%1,%2,%3};"
                 : "+f"(c[0]), "+f"(c[1]), "+f"(c[2]), "+f"(c[3])
                 : "r"(a[0]), "r"(a[1]), "r"(a[2]), "r"(a[3]), "r"(b[0]), "r"(b[1]));
}
__device__ __forceinline__ void split_bf16(float v, bf16& h, bf16& l) {
    h = __float2bfloat16(v);
    l = __float2bfloat16(v - __bfloat162float(h));
}
__device__ __forceinline__ void packhl(float a, float b, uint32_t& hi, uint32_t& lo) {
    __nv_bfloat162 hv, lv;
    split_bf16(a, hv.x, lv.x);
    split_bf16(b, hv.y, lv.y);
    hi = *(uint32_t*)&hv;
    lo = *(uint32_t*)&lv;
}
__device__ __forceinline__ float gelu_exact(float v) {
    return 0.5f * v * (1.0f + erff(v * 0.70710678118654752f));
}

// ---------------- fused double layernorm -> bf16 hi/lo ----------------
__global__ void ln_kernel(const float* __restrict__ x,
                          const float* __restrict__ g1, const float* __restrict__ b1,
                          const float* __restrict__ g2, const float* __restrict__ b2,
                          bf16* __restrict__ o1h, bf16* __restrict__ o1l,
                          bf16* __restrict__ o2h, bf16* __restrict__ o2l) {
    __shared__ float redS[8];
    __shared__ float redQ[8];
    const int row = blockIdx.x;
    const float* xr = x + (size_t)row * HID;
    const int t = threadIdx.x;
    float4 a = *(const float4*)(xr + t * 8);
    float4 b = *(const float4*)(xr + t * 8 + 4);
    float s  = a.x + a.y + a.z + a.w + b.x + b.y + b.z + b.w;
    float ss = a.x*a.x + a.y*a.y + a.z*a.z + a.w*a.w
             + b.x*b.x + b.y*b.y + b.z*b.z + b.w*b.w;
    #pragma unroll
    for (int o = 16; o; o >>= 1) {
        s  += __shfl_xor_sync(0xffffffffu, s,  o);
        ss += __shfl_xor_sync(0xffffffffu, ss, o);
    }
    if ((t & 31) == 0) { redS[t >> 5] = s; redQ[t >> 5] = ss; }
    __syncthreads();
    s = 0.f; ss = 0.f;
    #pragma unroll
    for (int i = 0; i < 8; i++) { s += redS[i]; ss += redQ[i]; }
    const float mu  = s * (1.0f / HID);
    const float var = ss * (1.0f / HID) - mu * mu;
    const float rs  = rsqrtf(var + 1e-5f);

    float vals[8] = {a.x,a.y,a.z,a.w,b.x,b.y,b.z,b.w};
    __align__(16) bf16 h1[8], l1[8], h2[8], l2[8];
    #pragma unroll
    for (int q = 0; q < 8; q++) {
        const int col = t * 8 + q;
        const float xn = (vals[q] - mu) * rs;
        split_bf16(xn * g1[col] + b1[col], h1[q], l1[q]);
        split_bf16(xn * g2[col] + b2[col], h2[q], l2[q]);
    }
    const size_t off = (size_t)row * HID + t * 8;
    *(uint4*)(o1h + off) = *(uint4*)h1;
    *(uint4*)(o1l + off) = *(uint4*)l1;
    *(uint4*)(o2h + off) = *(uint4*)h2;
    *(uint4*)(o2l + off) = *(uint4*)l2;
}

// ---------------- weight convert + transpose: W[K][N] -> T{h,l}[N][K] ------
__global__ void wconv_kernel(const float* __restrict__ W, bf16* __restrict__ Th,
                             bf16* __restrict__ Tl, int K, int N) {
    __shared__ float tile[32][33];
    const int n0 = blockIdx.x * 32, k0 = blockIdx.y * 32;
    const int tx = threadIdx.x, ty = threadIdx.y;  // 32 x 8
    #pragma unroll
    for (int i = 0; i < 4; i++)
        tile[ty + 8 * i][tx] = W[(size_t)(k0 + ty + 8 * i) * N + n0 + tx];
    __syncthreads();
    #pragma unroll
    for (int i = 0; i < 4; i++) {
        const float v = tile[tx][ty + 8 * i];
        const size_t idx = (size_t)(n0 + ty + 8 * i) * K + k0 + tx;
        bf16 h, l;
        split_bf16(v, h, l);
        Th[idx] = h; Tl[idx] = l;
    }
}

// ---------------- RoPE cos/sin table ----------------
__global__ void rope_tab_kernel(float* __restrict__ tab) {
    const int i = blockIdx.x * 256 + threadIdx.x;   // SS*16 entries
    const int s = i >> 4, fi = i & 15;
    const float inv = powf(10000.0f, -(float)fi * (1.0f / 16.0f));
    float sn, cs;
    sincosf((float)s * inv, &sn, &cs);
    tab[i * 2]     = cs;
    tab[i * 2 + 1] = sn;
}

// ---------------- mma.sync bf16-split GEMM, CTA 256x128, BK=64 -------------
// C[M,N] = A[M,K]*B^T (B stored as T[N][K]).  8 warps, warp tile 64x64.
// stage: Ah(256x72) Al(256x72) Bh(128x72) Bl(128x72) bf16 = 110592 B; x2 stages.
#define ROWP   72
#define A_ARR  36864u
#define B_ARR  18432u
#define STG_B  110592u
#define G_SMEM (2u * STG_B)

// EPI: 0 +bias->f32 | 1 gelu(+bias)->bf16 h/l | 2 +bias+add1+add2->f32
//      3 qkv: +bias, RoPE, q-scale, head-transpose -> 6 bf16 h/l arrays
template <int EPI>
__global__ void __launch_bounds__(256, 1) mma_gemm(
    const bf16* __restrict__ Ah, const bf16* __restrict__ Al,
    const bf16* __restrict__ Bh, const bf16* __restrict__ Bl,
    const float* __restrict__ bias,
    const float* __restrict__ add1, const float* __restrict__ add2,
    const float* __restrict__ rtab,
    float* __restrict__ Cf, bf16* __restrict__ Ch, bf16* __restrict__ Cl,
    bf16* __restrict__ o2h, bf16* __restrict__ o2l,
    bf16* __restrict__ o3h, bf16* __restrict__ o3l,
    int N, int K) {
    extern __shared__ char sm[];
    const uint32_t smb = smem_u32(sm);
    const int tid = threadIdx.x;
    const int lane = tid & 31;
    const int wm = (tid >> 5) & 3;     // 4 warps along M (64 rows each)
    const int wn = (tid >> 7);         // 2 warps along N (64 cols each)

    const size_t arow0 = (size_t)blockIdx.x * 256;
    const size_t brow0 = (size_t)blockIdx.y * 128;
    const bf16* pa_h = Ah + arow0 * K;
    const bf16* pa_l = Al + arow0 * K;
    const bf16* pb_h = Bh + brow0 * K;
    const bf16* pb_l = Bl + brow0 * K;
    const int nch = K >> 6;

    const uint32_t aoff = ((wm * 64 + (lane & 15)) * ROWP + (lane >> 4) * 8) * 2;
    const uint32_t boff = ((wn * 64 + (lane & 7) + ((lane >> 4) & 1) * 8) * ROWP
                           + ((lane >> 3) & 1) * 8) * 2;

    float acc[4][8][4];
    #pragma unroll
    for (int m = 0; m < 4; m++)
        #pragma unroll
        for (int n = 0; n < 8; n++)
            #pragma unroll
            for (int q = 0; q < 4; q++) acc[m][n][q] = 0.f;

    auto load_stage = [&](int stg, int k0) {
        const uint32_t sb = smb + (uint32_t)stg * STG_B;
        #pragma unroll
        for (int i = 0; i < 8; ++i) {          // A: 2048 chunks per array
            const int id = tid + i * 256;
            const int row = id >> 3, cc = id & 7;
            const uint32_t so = (uint32_t)(row * ROWP + cc * 8) * 2;
            const size_t go = (size_t)row * K + k0 + cc * 8;
            CP16(sb + so,         pa_h + go);
            CP16(sb + A_ARR + so, pa_l + go);
        }
        #pragma unroll
        for (int i = 0; i < 4; ++i) {          // B: 1024 chunks per array
            const int id = tid + i * 256;
            const int row = id >> 3, cc = id & 7;
            const uint32_t so = (uint32_t)(row * ROWP + cc * 8) * 2;
            const size_t go = (size_t)row * K + k0 + cc * 8;
            CP16(sb + 2 * A_ARR + so,         pb_h + go);
            CP16(sb + 2 * A_ARR + B_ARR + so, pb_l + go);
        }
    };

    load_stage(0, 0);
    CP_COMMIT();

    for (int c = 0; c < nch; ++c) {
        CP_WAIT0();
        __syncthreads();
        if (c + 1 < nch) {
            load_stage((c + 1) & 1, (c + 1) << 6);
            CP_COMMIT();
        }
        const uint32_t sb = smb + (uint32_t)(c & 1) * STG_B;
        #pragma unroll
        for (int ks = 0; ks < 4; ++ks) {
            const uint32_t kb = ks * 32;       // 16 elems * 2B
            uint32_t ah[4][4], bh[4][4];
            #pragma unroll
            for (int i = 0; i < 4; ++i)
                ldm_x4(ah[i], sb + aoff + kb + i * 16 * ROWP * 2);
            #pragma unroll
            for (int t2 = 0; t2 < 4; ++t2)
                ldm_x4(bh[t2], sb + 2 * A_ARR + boff + kb + t2 * 16 * ROWP * 2);
            #pragma unroll
            for (int m = 0; m < 4; ++m)
                #pragma unroll
                for (int n = 0; n < 8; ++n)
                    mma_bf16(acc[m][n], ah[m], &bh[n >> 1][(n & 1) * 2]);
            {
                uint32_t al[4][4];
                #pragma unroll
                for (int i = 0; i < 4; ++i)
                    ldm_x4(al[i], sb + A_ARR + aoff + kb + i * 16 * ROWP * 2);
                #pragma unroll
                for (int m = 0; m < 4; ++m)
                    #pragma unroll
                    for (int n = 0; n < 8; ++n)
                        mma_bf16(acc[m][n], al[m], &bh[n >> 1][(n & 1) * 2]);
            }
            {
                uint32_t bl[4][4];
                #pragma unroll
                for (int t2 = 0; t2 < 4; ++t2)
                    ldm_x4(bl[t2], sb + 2 * A_ARR + B_ARR + boff + kb + t2 * 16 * ROWP * 2);
                #pragma unroll
                for (int m = 0; m < 4; ++m)
                    #pragma unroll
                    for (int n = 0; n < 8; ++n)
                        mma_bf16(acc[m][n], ah[m], &bl[n >> 1][(n & 1) * 2]);
            }
        }
    }

    // ---------------- epilogue ----------------
    const int row_base = blockIdx.x * 256 + wm * 64;
    const int col_base = blockIdx.y * 128 + wn * 64;

    if (EPI == 3) {
        // qkv: bias, RoPE (d<32 of q/k sections), q scale, head-major split
        const int hh2 = col_base / 384;
        const int sub0 = col_base % 384;
        const int sect = sub0 >> 7;            // 0=q 1=k 2=v
        const int dbase = sub0 & 127;
        const bool ropeW = (dbase == 0) && (sect < 2);
        const float qsc = (sect == 0) ? 0.08838834764831845f : 1.0f;
        bf16* Oh = (sect == 0) ? Ch : (sect == 1) ? o2h : o3h;
        bf16* Ol = (sect == 0) ? Cl : (sect == 1) ? o2l : o3l;
        #pragma unroll
        for (int m = 0; m < 4; ++m) {
            const int r0 = row_base + m * 16 + (lane >> 2);
            const int r1 = r0 + 8;
            const int bb2 = r0 >> 11;
            const int s0 = r0 & (SS - 1), s1 = r1 & (SS - 1);
            float v[8][4];
            #pragma unroll
            for (int n = 0; n < 8; ++n) {
                const int cc = col_base + n * 8 + (lane & 3) * 2;
                const float b0 = bias[cc], b1 = bias[cc + 1];
                v[n][0] = acc[m][n][0] + b0; v[n][1] = acc[m][n][1] + b1;
                v[n][2] = acc[m][n][2] + b0; v[n][3] = acc[m][n][3] + b1;
            }
            if (ropeW) {
                float rp[4][4];
                #pragma unroll
                for (int n = 0; n < 4; ++n) {
                    const int dl = n * 8 + (lane & 3) * 2;   // 0..30 even
                    const bool first = dl < 16;
                    const int np = first ? n + 2 : n - 2;
                    const float sign = first ? -1.0f : 1.0f;
                    const int fi0 = dl & 15, fi1 = (dl + 1) & 15;
                    const float2 c00 = *(const float2*)(rtab + (s0 * 16 + fi0) * 2);
                    const float2 c01 = *(const float2*)(rtab + (s0 * 16 + fi1) * 2);
                    const float2 c10 = *(const float2*)(rtab + (s1 * 16 + fi0) * 2);
                    const float2 c11 = *(const float2*)(rtab + (s1 * 16 + fi1) * 2);
                    rp[n][0] = v[n][0] * c00.x + sign * v[np][0] * c00.y;
                    rp[n][1] = v[n][1] * c01.x + sign * v[np][1] * c01.y;
                    rp[n][2] = v[n][2] * c10.x + sign * v[np][2] * c10.y;
                    rp[n][3] = v[n][3] * c11.x + sign * v[np][3] * c11.y;
                }
                #pragma unroll
                for (int n = 0; n < 4; ++n)
                    #pragma unroll
                    for (int q = 0; q < 4; ++q) v[n][q] = rp[n][q];
            }
            const size_t base0 = (((size_t)bb2 * HH + hh2) * SS + s0) * HD;
            const size_t base1 = (((size_t)bb2 * HH + hh2) * SS + s1) * HD;
            #pragma unroll
            for (int n = 0; n < 8; ++n) {
                const int d = dbase + n * 8 + (lane & 3) * 2;
                uint32_t hi, lo;
                packhl(v[n][0] * qsc, v[n][1] * qsc, hi, lo);
                *(uint32_t*)(Oh + base0 + d) = hi;
                *(uint32_t*)(Ol + base0 + d) = lo;
                packhl(v[n][2] * qsc, v[n][3] * qsc, hi, lo);
                *(uint32_t*)(Oh + base1 + d) = hi;
                *(uint32_t*)(Ol + base1 + d) = lo;
            }
        }
        return;
    }

    #pragma unroll
    for (int m = 0; m < 4; ++m) {
        const int r0 = row_base + m * 16 + (lane >> 2);
        #pragma unroll
        for (int n = 0; n < 8; ++n) {
            const int cc = col_base + n * 8 + (lane & 3) * 2;
            const float b0 = bias[cc], b1 = bias[cc + 1];
            float v0 = acc[m][n][0] + b0, v1 = acc[m][n][1] + b1;
            float v2 = acc[m][n][2] + b0, v3 = acc[m][n][3] + b1;
            const size_t off0 = (size_t)r0 * N + cc;
            const size_t off1 = (size_t)(r0 + 8) * N + cc;
            if (EPI == 1) {
                uint32_t hi, lo;
                packhl(gelu_exact(v0), gelu_exact(v1), hi, lo);
                *(uint32_t*)(Ch + off0) = hi;
                *(uint32_t*)(Cl + off0) = lo;
                packhl(gelu_exact(v2), gelu_exact(v3), hi, lo);
                *(uint32_t*)(Ch + off1) = hi;
                *(uint32_t*)(Cl + off1) = lo;
            } else {
                if (EPI == 2) {
                    const float2 x0 = *(const float2*)(add1 + off0);
                    const float2 y0 = *(const float2*)(add2 + off0);
                    const float2 x1 = *(const float2*)(add1 + off1);
                    const float2 y1 = *(const float2*)(add2 + off1);
                    v0 += x0.x + y0.x; v1 += x0.y + y0.y;
                    v2 += x1.x + y1.x; v3 += x1.y + y1.y;
                }
                *(float2*)(Cf + off0) = make_float2(v0, v1);
                *(float2*)(Cf + off1) = make_float2(v2, v3);
            }
        }
    }
}

// ---------------- causal flash attention via mma.sync, BQ=128 --------------
#define AST   136
#define ATILE (64 * AST * 2)
#define AQ_H  0
#define AQ_L  (2 * ATILE)
#define ASTAGE0 (4 * ATILE)
#define ASTG_B  (4 * ATILE)
#define A_SMEM  (4 * ATILE + 2 * ASTG_B)

__global__ void __launch_bounds__(256, 1) attn_mma_kernel(
    const bf16* __restrict__ Qh, const bf16* __restrict__ Ql,
    const bf16* __restrict__ Kh, const bf16* __restrict__ Kl,
    const bf16* __restrict__ Vh, const bf16* __restrict__ Vl,
    bf16* __restrict__ ctxh, bf16* __restrict__ ctxl) {
    extern __shared__ char sm[];
    const uint32_t smb = smem_u32(sm);
    const int qt = gridDim.x - 1 - blockIdx.x;
    const int bhid = blockIdx.y;
    const int b = bhid >> 4, h = bhid & 15;
    const int tid = threadIdx.x;
    const int lane = tid & 31;
    const int w = tid >> 5;

    const size_t headbase = (size_t)bhid * SS * HD;

    auto ldq = [&]() {
        const size_t gb = headbase + (size_t)qt * 128 * HD;
        #pragma unroll
        for (int i = 0; i < 8; i++) {
            const int c = tid + i * 256;
            const int row = c >> 4, ch = c & 15;
            const uint32_t so = row * (AST * 2) + ch * 16;
            const size_t go = gb + (size_t)row * HD + ch * 8;
            CP16(smb + AQ_H + so, Qh + go);
            CP16(smb + AQ_L + so, Ql + go);
        }
    };
    auto ldkv = [&](int kt, int stg) {
        const uint32_t sb = smb + ASTAGE0 + (uint32_t)stg * ASTG_B;
        const size_t gb = headbase + (size_t)kt * 64 * HD;
        #pragma unroll
        for (int i = 0; i < 4; i++) {
            const int c = tid + i * 256;
            const int row = c >> 4, ch = c & 15;
            const uint32_t so = row * (AST * 2) + ch * 16;
            const size_t go = gb + (size_t)row * HD + ch * 8;
            CP16(sb + so,             Kh + go);
            CP16(sb + ATILE + so,     Kl + go);
            CP16(sb + 2 * ATILE + so, Vh + go);
            CP16(sb + 3 * ATILE + so, Vl + go);
        }
    };

    const uint32_t qa_off = ((w * 16 + (lane & 15)) * AST + (lane >> 4) * 8) * 2;
    const int lm = lane >> 3, li = lane & 7;
    const uint32_t kb_off = (((lm >> 1) * 8 + li) * AST + (lm & 1) * 8) * 2;
    const uint32_t vb_off = (((lm & 1) * 8 + li) * AST + (lm >> 1) * 8) * 2;

    float oacc[16][4];
    #pragma unroll
    for (int t = 0; t < 16; t++)
        #pragma unroll
        for (int q = 0; q < 4; q++) oacc[t][q] = 0.f;
    float m0 = -1e30f, m1 = -1e30f, l0 = 0.f, l1 = 0.f;
    const int qrow0 = qt * 128 + w * 16 + (lane >> 2);
    const int qrow1 = qrow0 + 8;
    const int nkt = 2 * qt + 2;

    ldq();
    ldkv(0, 0);
    CP_COMMIT();

    for (int kt = 0; kt < nkt; ++kt) {
        if (kt + 1 < nkt) {
            ldkv(kt + 1, (kt + 1) & 1);
            CP_COMMIT();
            CP_WAIT1();
        } else {
            CP_WAIT0();
        }
        __syncthreads();
        const uint32_t sb = smb + ASTAGE0 + (uint32_t)(kt & 1) * ASTG_B;

        float sacc[8][4];
        #pragma unroll
        for (int j = 0; j < 8; j++)
            #pragma unroll
            for (int q = 0; q < 4; q++) sacc[j][q] = 0.f;

        #pragma unroll
        for (int ks = 0; ks < 8; ++ks) {
            uint32_t ah[4], al[4], kfh[8][2], kfl[8][2];
            ldm_x4(ah, smb + AQ_H + qa_off + ks * 32);
            ldm_x4(al, smb + AQ_L + qa_off + ks * 32);
            #pragma unroll
            for (int jp = 0; jp < 4; ++jp) {
                uint32_t r[4];
                ldm_x4(r, sb + kb_off + (jp * 16 * AST + ks * 16) * 2);
                kfh[2*jp][0] = r[0]; kfh[2*jp][1] = r[1];
                kfh[2*jp+1][0] = r[2]; kfh[2*jp+1][1] = r[3];
                ldm_x4(r, sb + ATILE + kb_off + (jp * 16 * AST + ks * 16) * 2);
                kfl[2*jp][0] = r[0]; kfl[2*jp][1] = r[1];
                kfl[2*jp+1][0] = r[2]; kfl[2*jp+1][1] = r[3];
            }
            #pragma unroll
            for (int j = 0; j < 8; ++j) mma_bf16(sacc[j], ah, kfh[j]);
            #pragma unroll
            for (int j = 0; j < 8; ++j) mma_bf16(sacc[j], al, kfh[j]);
            #pragma unroll
            for (int j = 0; j < 8; ++j) mma_bf16(sacc[j], ah, kfl[j]);
        }

        if (kt >= 2 * qt) {
            #pragma unroll
            for (int j = 0; j < 8; ++j) {
                const int c0 = kt * 64 + j * 8 + (lane & 3) * 2;
                if (c0     > qrow0) sacc[j][0] = -1e30f;
                if (c0 + 1 > qrow0) sacc[j][1] = -1e30f;
                if (c0     > qrow1) sacc[j][2] = -1e30f;
                if (c0 + 1 > qrow1) sacc[j][3] = -1e30f;
            }
        }

        float mx0 = -1e30f, mx1 = -1e30f;
        #pragma unroll
        for (int j = 0; j < 8; ++j) {
            mx0 = fmaxf(mx0, fmaxf(sacc[j][0], sacc[j][1]));
            mx1 = fmaxf(mx1, fmaxf(sacc[j][2], sacc[j][3]));
        }
        #pragma unroll
        for (int o = 1; o < 4; o <<= 1) {
            mx0 = fmaxf(mx0, __shfl_xor_sync(0xffffffffu, mx0, o));
            mx1 = fmaxf(mx1, __shfl_xor_sync(0xffffffffu, mx1, o));
        }
        const float mn0 = fmaxf(m0, mx0), mn1 = fmaxf(m1, mx1);
        const float e0 = __expf(m0 - mn0), e1 = __expf(m1 - mn1);
        m0 = mn0; m1 = mn1;
        float rs0 = 0.f, rs1 = 0.f;
        #pragma unroll
        for (int j = 0; j < 8; ++j) {
            sacc[j][0] = __expf(sacc[j][0] - mn0); rs0 += sacc[j][0];
            sacc[j][1] = __expf(sacc[j][1] - mn0); rs0 += sacc[j][1];
            sacc[j][2] = __expf(sacc[j][2] - mn1); rs1 += sacc[j][2];
            sacc[j][3] = __expf(sacc[j][3] - mn1); rs1 += sacc[j][3];
        }
        #pragma unroll
        for (int o = 1; o < 4; o <<= 1) {
            rs0 += __shfl_xor_sync(0xffffffffu, rs0, o);
            rs1 += __shfl_xor_sync(0xffffffffu, rs1, o);
        }
        l0 = l0 * e0 + rs0;
        l1 = l1 * e1 + rs1;
        #pragma unroll
        for (int t = 0; t < 16; t++) {
            oacc[t][0] *= e0; oacc[t][1] *= e0;
            oacc[t][2] *= e1; oacc[t][3] *= e1;
        }

        #pragma unroll
        for (int c = 0; c < 4; ++c) {
            uint32_t pah[4], pal[4];
            packhl(sacc[2*c][0],   sacc[2*c][1],   pah[0], pal[0]);
            packhl(sacc[2*c][2],   sacc[2*c][3],   pah[1], pal[1]);
            packhl(sacc[2*c+1][0], sacc[2*c+1][1], pah[2], pal[2]);
            packhl(sacc[2*c+1][2], sacc[2*c+1][3], pah[3], pal[3]);
            #pragma unroll
            for (int tp = 0; tp < 8; ++tp) {
                uint32_t rvh[4], rvl[4];
                ldm_x4_t(rvh, sb + 2 * ATILE + vb_off + (c * 16 * AST + tp * 16) * 2);
                ldm_x4_t(rvl, sb + 3 * ATILE + vb_off + (c * 16 * AST + tp * 16) * 2);
                mma_bf16(oacc[2*tp],   pah, &rvh[0]);
                mma_bf16(oacc[2*tp],   pal, &rvh[0]);
                mma_bf16(oacc[2*tp],   pah, &rvl[0]);
                mma_bf16(oacc[2*tp+1], pah, &rvh[2]);
                mma_bf16(oacc[2*tp+1], pal, &rvh[2]);
                mma_bf16(oacc[2*tp+1], pah, &rvl[2]);
            }
        }
        __syncthreads();
    }

    const float inv0 = 1.0f / l0, inv1 = 1.0f / l1;
    const size_t ob0 = ((size_t)b * SS + qrow0) * HID + h * HD;
    const size_t ob1 = ((size_t)b * SS + qrow1) * HID + h * HD;
    #pragma unroll
    for (int t = 0; t < 16; ++t) {
        const int d = t * 8 + (lane & 3) * 2;
        uint32_t hi, lo;
        packhl(oacc[t][0] * inv0, oacc[t][1] * inv0, hi, lo);
        *(uint32_t*)(ctxh + ob0 + d) = hi;
        *(uint32_t*)(ctxl + ob0 + d) = lo;
        packhl(oacc[t][2] * inv1, oacc[t][3] * inv1, hi, lo);
        *(uint32_t*)(ctxh + ob1 + d) = hi;
        *(uint32_t*)(ctxl + ob1 + d) = lo;
    }
}

// ---------------- launch ----------------
extern "C" void kernel_launch(void* const* d_in, const int* in_sizes, int n_in,
                              void* d_out, int out_size) {
    const float* hid   = (const float*)d_in[0];
    const float* ln1g  = (const float*)d_in[1];
    const float* ln1b  = (const float*)d_in[2];
    const float* ln2g  = (const float*)d_in[3];
    const float* ln2b  = (const float*)d_in[4];
    const float* Wqkv  = (const float*)d_in[5];
    const float* bqkv  = (const float*)d_in[6];
    const float* Wo    = (const float*)d_in[7];
    const float* bo    = (const float*)d_in[8];
    const float* Wfc   = (const float*)d_in[9];
    const float* bfc   = (const float*)d_in[10];
    const float* Wproj = (const float*)d_in[11];
    const float* bproj = (const float*)d_in[12];
    float* out = (float*)d_out;

    float *att, *rope;
    bf16 *ln1h, *ln1l, *ln2h, *ln2l, *ctxh, *ctxl, *fch, *fcl;
    bf16 *Qh, *Ql, *Kh, *Kl, *Vh, *Vl;
    bf16 *wqkvh, *wqkvl, *woh, *wol, *wfch, *wfcl, *wprojh, *wprojl;
    cudaGetSymbolAddress((void**)&att, g_att);
    cudaGetSymbolAddress((void**)&rope, g_rope);
    cudaGetSymbolAddress((void**)&ln1h, g_ln1h);
    cudaGetSymbolAddress((void**)&ln1l, g_ln1l);
    cudaGetSymbolAddress((void**)&ln2h, g_ln2h);
    cudaGetSymbolAddress((void**)&ln2l, g_ln2l);
    cudaGetSymbolAddress((void**)&ctxh, g_ctxh);
    cudaGetSymbolAddress((void**)&ctxl, g_ctxl);
    cudaGetSymbolAddress((void**)&fch, g_fch);
    cudaGetSymbolAddress((void**)&fcl, g_fcl);
    cudaGetSymbolAddress((void**)&Qh, g_Qh);
    cudaGetSymbolAddress((void**)&Ql, g_Ql);
    cudaGetSymbolAddress((void**)&Kh, g_Kh);
    cudaGetSymbolAddress((void**)&Kl, g_Kl);
    cudaGetSymbolAddress((void**)&Vh, g_Vh);
    cudaGetSymbolAddress((void**)&Vl, g_Vl);
    cudaGetSymbolAddress((void**)&wqkvh, g_wqkvh);
    cudaGetSymbolAddress((void**)&wqkvl, g_wqkvl);
    cudaGetSymbolAddress((void**)&woh, g_woh);
    cudaGetSymbolAddress((void**)&wol, g_wol);
    cudaGetSymbolAddress((void**)&wfch, g_wfch);
    cudaGetSymbolAddress((void**)&wfcl, g_wfcl);
    cudaGetSymbolAddress((void**)&wprojh, g_wprojh);
    cudaGetSymbolAddress((void**)&wprojl, g_wprojl);

    cudaFuncSetAttribute(mma_gemm<0>, cudaFuncAttributeMaxDynamicSharedMemorySize, G_SMEM);
    cudaFuncSetAttribute(mma_gemm<1>, cudaFuncAttributeMaxDynamicSharedMemorySize, G_SMEM);
    cudaFuncSetAttribute(mma_gemm<2>, cudaFuncAttributeMaxDynamicSharedMemorySize, G_SMEM);
    cudaFuncSetAttribute(mma_gemm<3>, cudaFuncAttributeMaxDynamicSharedMemorySize, G_SMEM);
    cudaFuncSetAttribute(attn_mma_kernel, cudaFuncAttributeMaxDynamicSharedMemorySize, A_SMEM);

    // weight conversions + rope table
    wconv_kernel<<<dim3(3 * HID / 32, HID / 32), dim3(32, 8)>>>(Wqkv, wqkvh, wqkvl, HID, 3 * HID);
    wconv_kernel<<<dim3(HID / 32, HID / 32),     dim3(32, 8)>>>(Wo,   woh,   wol,   HID, HID);
    wconv_kernel<<<dim3(FF / 32, HID / 32),      dim3(32, 8)>>>(Wfc,  wfch,  wfcl,  HID, FF);
    wconv_kernel<<<dim3(HID / 32, FF / 32),      dim3(32, 8)>>>(Wproj, wprojh, wprojl, FF, HID);
    rope_tab_kernel<<<SS * 16 / 256, 256>>>(rope);

    // 1. LN1 + LN2 fused -> bf16 hi/lo
    ln_kernel<<<NTOK, 256>>>(hid, ln1g, ln1b, ln2g, ln2b, ln1h, ln1l, ln2h, ln2l);

    // 2. QKV gemm + fused bias/RoPE/scale/head-transpose -> Q/K/V bf16 hi/lo
    mma_gemm<3><<<dim3(NTOK / 256, 3 * HID / 128), 256, G_SMEM>>>(
        ln1h, ln1l, wqkvh, wqkvl, bqkv, nullptr, nullptr, rope,
        nullptr, Qh, Ql, Kh, Kl, Vh, Vl, 3 * HID, HID);

    // 3. causal attention (mma.sync, BQ=128) -> ctx bf16 hi/lo
    attn_mma_kernel<<<dim3(SS / 128, BB * HH), 256, A_SMEM>>>(
        Qh, Ql, Kh, Kl, Vh, Vl, ctxh, ctxl);

    // 4. attn_out = ctx @ W_o + b_o -> fp32
    mma_gemm<0><<<dim3(NTOK / 256, HID / 128), 256, G_SMEM>>>(
        ctxh, ctxl, woh, wol, bo, nullptr, nullptr, nullptr,
        att, nullptr, nullptr, nullptr, nullptr, nullptr, nullptr, HID, HID);

    // 5. fc = gelu(ln2 @ W_fc + b_fc) -> bf16 hi/lo
    mma_gemm<1><<<dim3(NTOK / 256, FF / 128), 256, G_SMEM>>>(
        ln2h, ln2l, wfch, wfcl, bfc, nullptr, nullptr, nullptr,
        nullptr, fch, fcl, nullptr, nullptr, nullptr, nullptr, FF, HID);

    // 6. out = fc @ W_proj + b_proj + attn_out + hidden
    mma_gemm<2><<<dim3(NTOK / 256, HID / 128), 256, G_SMEM>>>(
        fch, fcl, wprojh, wprojl, bproj, att, hid, nullptr,
        out, nullptr, nullptr, nullptr, nullptr, nullptr, nullptr, HID, FF);
}